// round 2
// baseline (speedup 1.0000x reference)
#include <cuda_runtime.h>
#include <cuda_bf16.h>
#include <math.h>

// Problem constants
#define B_SZ 4
#define T_SZ 2048
#define DM   1024
#define NH   16
#define HD   64
#define MROWS (B_SZ * T_SZ)   // 8192

// ---------------- scratch (allocation-free) ----------------
__device__ float g_Q[MROWS * DM];
__device__ float g_K[MROWS * DM];
__device__ float g_V[MROWS * DM];
__device__ float g_O[MROWS * DM];

// ---------------- NT GEMM: C[M,N] = A[M,K] * B[N,K]^T (+bias) ----------------
// BM=BN=64, BK=16, 256 threads, 4x4 micro-tile per thread.
#define GBM 64
#define GBN 64
#define GBK 16
#define GPAD 68   // row stride in floats (272B = 17*16B, keeps float4 alignment)

__global__ __launch_bounds__(256)
void gemm_nt_kernel(const float* __restrict__ A, const float* __restrict__ Bm,
                    float* __restrict__ C, const float* __restrict__ bias,
                    int M, int N, int K)
{
    __shared__ __align__(16) float As[GBK * GPAD];
    __shared__ __align__(16) float Bs[GBK * GPAD];

    const int tid = threadIdx.x;
    const int tx = tid & 15;        // 0..15 -> N micro
    const int ty = tid >> 4;        // 0..15 -> M micro
    const int row0 = blockIdx.y * GBM;
    const int col0 = blockIdx.x * GBN;

    const int lr  = tid >> 2;        // 0..63 row within tile
    const int lc4 = (tid & 3) * 4;   // 0,4,8,12 col within k-tile

    const float* Ag = A + (size_t)(row0 + lr) * K + lc4;
    const float* Bg = Bm + (size_t)(col0 + lr) * K + lc4;

    float acc[4][4];
    #pragma unroll
    for (int i = 0; i < 4; ++i)
        #pragma unroll
        for (int j = 0; j < 4; ++j) acc[i][j] = 0.f;

    for (int kt = 0; kt < K; kt += GBK) {
        float4 av = *(const float4*)(Ag + kt);
        float4 bv = *(const float4*)(Bg + kt);
        __syncthreads();
        As[(lc4 + 0) * 1 + 0]; // no-op to keep layout clear
        As[(lc4 + 0) * GPAD + lr] = av.x;
        As[(lc4 + 1) * GPAD + lr] = av.y;
        As[(lc4 + 2) * GPAD + lr] = av.z;
        As[(lc4 + 3) * GPAD + lr] = av.w;
        Bs[(lc4 + 0) * GPAD + lr] = bv.x;
        Bs[(lc4 + 1) * GPAD + lr] = bv.y;
        Bs[(lc4 + 2) * GPAD + lr] = bv.z;
        Bs[(lc4 + 3) * GPAD + lr] = bv.w;
        __syncthreads();

        #pragma unroll
        for (int k = 0; k < GBK; ++k) {
            float4 a = *(const float4*)&As[k * GPAD + ty * 4];
            float4 b = *(const float4*)&Bs[k * GPAD + tx * 4];
            acc[0][0] += a.x * b.x; acc[0][1] += a.x * b.y; acc[0][2] += a.x * b.z; acc[0][3] += a.x * b.w;
            acc[1][0] += a.y * b.x; acc[1][1] += a.y * b.y; acc[1][2] += a.y * b.z; acc[1][3] += a.y * b.w;
            acc[2][0] += a.z * b.x; acc[2][1] += a.z * b.y; acc[2][2] += a.z * b.z; acc[2][3] += a.z * b.w;
            acc[3][0] += a.w * b.x; acc[3][1] += a.w * b.y; acc[3][2] += a.w * b.z; acc[3][3] += a.w * b.w;
        }
    }

    float4 bb = make_float4(0.f, 0.f, 0.f, 0.f);
    if (bias) {
        bb = *(const float4*)&bias[col0 + tx * 4];
    }
    #pragma unroll
    for (int i = 0; i < 4; ++i) {
        float4 o;
        o.x = acc[i][0] + bb.x;
        o.y = acc[i][1] + bb.y;
        o.z = acc[i][2] + bb.z;
        o.w = acc[i][3] + bb.w;
        *(float4*)&C[(size_t)(row0 + ty * 4 + i) * N + col0 + tx * 4] = o;
    }
}

// ---------------- Flash attention (fp32, exact online softmax) ----------------
// Block: 128 threads, each thread owns one full query row (q[64], acc[64] in regs).
// Loop over key tiles of 64, K/V tiles staged in smem (broadcast reads),
// scores staged in smem with stride 65 (conflict-free per-thread rows).
#define AT_BM 128
#define AT_BN 64
#define AT_SMEM (AT_BN * 16 * 16 * 2 + AT_BM * 65 * 4)  // Ks + Vs (float4) + Ss

__global__ __launch_bounds__(AT_BM)
void attn_kernel(const float* __restrict__ Q, const float* __restrict__ K,
                 const float* __restrict__ V, float* __restrict__ O)
{
    extern __shared__ __align__(16) char smem_raw[];
    float4* Ks = (float4*)smem_raw;                       // [AT_BN][16]
    float4* Vs = Ks + AT_BN * 16;                         // [AT_BN][16]
    float*  Ss = (float*)(Vs + AT_BN * 16);               // [AT_BM][65]

    const int tid = threadIdx.x;
    const int h = blockIdx.y;
    const int b = blockIdx.z;
    const int qrow = blockIdx.x * AT_BM + tid;            // global t index

    const size_t base = ((size_t)b * T_SZ) * DM + h * HD;

    // load q row (registers)
    float q[HD];
    {
        const float4* qg = (const float4*)(Q + base + (size_t)qrow * DM);
        #pragma unroll
        for (int d = 0; d < 16; ++d) {
            float4 v = qg[d];
            q[4*d+0] = v.x; q[4*d+1] = v.y; q[4*d+2] = v.z; q[4*d+3] = v.w;
        }
    }

    float acc[HD];
    #pragma unroll
    for (int d = 0; d < HD; ++d) acc[d] = 0.f;
    float m = -1e30f;
    float l = 0.f;

    const int n_tiles = T_SZ / AT_BN;   // 32
    for (int kt = 0; kt < n_tiles; ++kt) {
        __syncthreads();
        // load K/V tile: 64 rows x 16 float4 each
        {
            const int krow0 = kt * AT_BN;
            #pragma unroll
            for (int i = 0; i < (AT_BN * 16) / AT_BM; ++i) {   // 8 iters
                int idx = tid + i * AT_BM;
                int r = idx >> 4;
                int c = idx & 15;
                const float4* kg = (const float4*)(K + base + (size_t)(krow0 + r) * DM);
                const float4* vg = (const float4*)(V + base + (size_t)(krow0 + r) * DM);
                Ks[r * 16 + c] = kg[c];
                Vs[r * 16 + c] = vg[c];
            }
        }
        __syncthreads();

        // pass 1: scores + running max
        float mt = m;
        for (int j = 0; j < AT_BN; ++j) {
            float s = 0.f;
            #pragma unroll
            for (int d = 0; d < 16; ++d) {
                float4 kk = Ks[j * 16 + d];
                s += q[4*d+0] * kk.x;
                s += q[4*d+1] * kk.y;
                s += q[4*d+2] * kk.z;
                s += q[4*d+3] * kk.w;
            }
            s *= 0.125f;                  // 1/sqrt(64)
            Ss[tid * 65 + j] = s;
            mt = fmaxf(mt, s);
        }

        // rescale old state
        float corr = __expf(m - mt);
        l *= corr;
        #pragma unroll
        for (int d = 0; d < HD; ++d) acc[d] *= corr;

        // pass 2: exp + PV accumulate
        for (int j = 0; j < AT_BN; ++j) {
            float p = __expf(Ss[tid * 65 + j] - mt);
            l += p;
            #pragma unroll
            for (int d = 0; d < 16; ++d) {
                float4 vv = Vs[j * 16 + d];
                acc[4*d+0] += p * vv.x;
                acc[4*d+1] += p * vv.y;
                acc[4*d+2] += p * vv.z;
                acc[4*d+3] += p * vv.w;
            }
        }
        m = mt;
    }

    // write out: O[b, qrow, h*64 + d] = acc/(l + eps)
    float inv = 1.f / (l + 1e-8f);
    float4* og = (float4*)(O + base + (size_t)qrow * DM);
    #pragma unroll
    for (int d = 0; d < 16; ++d) {
        float4 o;
        o.x = acc[4*d+0] * inv;
        o.y = acc[4*d+1] * inv;
        o.z = acc[4*d+2] * inv;
        o.w = acc[4*d+3] * inv;
        og[d] = o;
    }
}

// ---------------- launch ----------------
extern "C" void kernel_launch(void* const* d_in, const int* in_sizes, int n_in,
                              void* d_out, int out_size)
{
    const float* x  = (const float*)d_in[0];
    const float* Wq = (const float*)d_in[1];
    const float* Wk = (const float*)d_in[2];
    const float* Wv = (const float*)d_in[3];
    const float* Wo = (const float*)d_in[4];
    const float* bo = (const float*)d_in[5];
    float* out = (float*)d_out;

    float *qb, *kb, *vb, *ob;
    cudaGetSymbolAddress((void**)&qb, g_Q);
    cudaGetSymbolAddress((void**)&kb, g_K);
    cudaGetSymbolAddress((void**)&vb, g_V);
    cudaGetSymbolAddress((void**)&ob, g_O);

    static int smem_set = 0;
    if (!smem_set) {
        cudaFuncSetAttribute(attn_kernel, cudaFuncAttributeMaxDynamicSharedMemorySize, AT_SMEM);
        smem_set = 1;
    }

    dim3 ggrid(DM / GBN, MROWS / GBM);   // (16, 128)
    gemm_nt_kernel<<<ggrid, 256>>>(x, Wq, qb, nullptr, MROWS, DM, DM);
    gemm_nt_kernel<<<ggrid, 256>>>(x, Wk, kb, nullptr, MROWS, DM, DM);
    gemm_nt_kernel<<<ggrid, 256>>>(x, Wv, vb, nullptr, MROWS, DM, DM);

    dim3 agrid(T_SZ / AT_BM, NH, B_SZ);  // (16, 16, 4)
    attn_kernel<<<agrid, AT_BM, AT_SMEM>>>(qb, kb, vb, ob);

    gemm_nt_kernel<<<ggrid, 256>>>(ob, Wo, out, bo, MROWS, DM, DM);
}

// round 6
// speedup vs baseline: 1.2723x; 1.2723x over previous
#include <cuda_runtime.h>
#include <cuda_bf16.h>
#include <cstdint>
#include <math.h>

// Problem constants
#define B_SZ 4
#define T_SZ 2048
#define DM   1024
#define NH   16
#define HD   64
#define MROWS (B_SZ * T_SZ)   // 8192
#define NELEM (MROWS * DM)

// ---------------- scratch (allocation-free) ----------------
__device__ float g_Q[NELEM];
__device__ float g_K[NELEM];
__device__ float g_V[NELEM];
__device__ float g_O[NELEM];

__device__ __nv_bfloat16 g_xh[NELEM];
__device__ __nv_bfloat16 g_xl[NELEM];
__device__ __nv_bfloat16 g_oh[NELEM];
__device__ __nv_bfloat16 g_ol[NELEM];
__device__ __nv_bfloat16 g_wqh[DM * DM];
__device__ __nv_bfloat16 g_wql[DM * DM];
__device__ __nv_bfloat16 g_wkh[DM * DM];
__device__ __nv_bfloat16 g_wkl[DM * DM];
__device__ __nv_bfloat16 g_wvh[DM * DM];
__device__ __nv_bfloat16 g_wvl[DM * DM];
__device__ __nv_bfloat16 g_woh[DM * DM];
__device__ __nv_bfloat16 g_wol[DM * DM];

// ---------------- helpers ----------------
__device__ __forceinline__ uint32_t smem_u32(const void* p) {
    uint32_t a;
    asm("{ .reg .u64 t; cvta.to.shared.u64 t, %1; cvt.u32.u64 %0, t; }" : "=r"(a) : "l"(p));
    return a;
}

// ldmatrix x4: 4 8x8 b16 matrices, one 16B row-address per lane
#define LDSM_X4(r, addr) \
    asm volatile("ldmatrix.sync.aligned.m8n8.x4.shared.b16 {%0,%1,%2,%3}, [%4];" \
        : "=r"((r)[0]), "=r"((r)[1]), "=r"((r)[2]), "=r"((r)[3]) : "r"(addr))

// D += A*B  (m16n8k16, bf16 in, fp32 accum)
#define MMA_BF16(d, a, b) \
    asm volatile("mma.sync.aligned.m16n8k16.row.col.f32.bf16.bf16.f32 " \
        "{%0,%1,%2,%3}, {%4,%5,%6,%7}, {%8,%9}, {%0,%1,%2,%3};" \
        : "+f"((d)[0]), "+f"((d)[1]), "+f"((d)[2]), "+f"((d)[3]) \
        : "r"((a)[0]), "r"((a)[1]), "r"((a)[2]), "r"((a)[3]), "r"((b)[0]), "r"((b)[1]))

// ---------------- split fp32 -> bf16 hi/lo ----------------
__global__ __launch_bounds__(256)
void split_kernel(const float* __restrict__ src, __nv_bfloat16* __restrict__ hi,
                  __nv_bfloat16* __restrict__ lo, int n4)
{
    int i = blockIdx.x * blockDim.x + threadIdx.x;
    if (i >= n4) return;
    float4 v = ((const float4*)src)[i];
    __nv_bfloat16 h0 = __float2bfloat16(v.x);
    __nv_bfloat16 h1 = __float2bfloat16(v.y);
    __nv_bfloat16 h2 = __float2bfloat16(v.z);
    __nv_bfloat16 h3 = __float2bfloat16(v.w);
    __nv_bfloat16 l0 = __float2bfloat16(v.x - __bfloat162float(h0));
    __nv_bfloat16 l1 = __float2bfloat16(v.y - __bfloat162float(h1));
    __nv_bfloat16 l2 = __float2bfloat16(v.z - __bfloat162float(h2));
    __nv_bfloat16 l3 = __float2bfloat16(v.w - __bfloat162float(h3));
    ((__nv_bfloat162*)hi)[2*i]   = __nv_bfloat162(h0, h1);
    ((__nv_bfloat162*)hi)[2*i+1] = __nv_bfloat162(h2, h3);
    ((__nv_bfloat162*)lo)[2*i]   = __nv_bfloat162(l0, l1);
    ((__nv_bfloat162*)lo)[2*i+1] = __nv_bfloat162(l2, l3);
}

// ---------------- mma.sync split-bf16 NT GEMM ----------------
// C[M,ldc] 128x128 tile = Ah*Bh^T + Ah*Bl^T + Al*Bh^T (+bias). A,B K-major.
#define GBM 128
#define GBN 128
#define GBK 64
#define OP_BYTES (GBM * GBK * 2)      // 16384 per operand tile
#define OFF_AH 0
#define OFF_AL (OP_BYTES)
#define OFF_BH (2 * OP_BYTES)
#define OFF_BL (3 * OP_BYTES)
#define GEMM_SMEM (4 * OP_BYTES)      // 65536

__global__ __launch_bounds__(256)
void gemm_mma_kernel(const __nv_bfloat16* __restrict__ Ah, const __nv_bfloat16* __restrict__ Al,
                     const __nv_bfloat16* __restrict__ Bh, const __nv_bfloat16* __restrict__ Bl,
                     float* __restrict__ C, const float* __restrict__ bias, int Kdim, int ldc)
{
    extern __shared__ __align__(128) char smem[];
    const uint32_t sb = smem_u32(smem);

    const int tid  = threadIdx.x;
    const int warp = tid >> 5;
    const int lane = tid & 31;
    const int wm = warp & 1;          // 0..1  (64 rows each)
    const int wn = warp >> 1;         // 0..3  (32 cols each)
    const int row0 = blockIdx.y * GBM;
    const int col0 = blockIdx.x * GBN;

    float acc[4][4][4];
    #pragma unroll
    for (int a = 0; a < 4; ++a)
        #pragma unroll
        for (int b = 0; b < 4; ++b)
            #pragma unroll
            for (int c = 0; c < 4; ++c) acc[a][b][c] = 0.f;

    const int sub = lane >> 3;        // 0..3 (ldmatrix sub-matrix)
    const int l7  = lane & 7;

    const int nchunk = Kdim / GBK;
    for (int kc = 0; kc < nchunk; ++kc) {
        if (kc) __syncthreads();
        // stage 4 operand tiles: 128 rows x 8 16B-chunks each, XOR swizzle
        {
            const int cc = tid & 7;
            #pragma unroll
            for (int i = 0; i < 4; ++i) {
                const int rr = (tid >> 3) + i * 32;
                const uint32_t so = (uint32_t)(rr * 128 + ((cc ^ (rr & 7)) << 4));
                const size_t ga = (size_t)(row0 + rr) * Kdim + kc * GBK + cc * 8;
                const size_t gb = (size_t)(col0 + rr) * Kdim + kc * GBK + cc * 8;
                *(uint4*)(smem + OFF_AH + so) = *(const uint4*)(Ah + ga);
                *(uint4*)(smem + OFF_AL + so) = *(const uint4*)(Al + ga);
                *(uint4*)(smem + OFF_BH + so) = *(const uint4*)(Bh + gb);
                *(uint4*)(smem + OFF_BL + so) = *(const uint4*)(Bl + gb);
            }
        }
        __syncthreads();

        #pragma unroll
        for (int ks = 0; ks < 4; ++ks) {
            uint32_t ah[4][4], al[4][4], bf[4][2];
            // A fragments (hi & lo): 4 m-subtiles of 16 rows
            #pragma unroll
            for (int mt = 0; mt < 4; ++mt) {
                const int r  = wm * 64 + mt * 16 + ((sub & 1) << 3) + l7;
                const int ch = ks * 2 + (sub >> 1);
                const uint32_t ad = sb + (uint32_t)(r * 128 + ((ch ^ (r & 7)) << 4));
                LDSM_X4(ah[mt], ad + OFF_AH);
                LDSM_X4(al[mt], ad + OFF_AL);
            }
            // B hi fragments: 4 n-subtiles of 8 rows (two per ldmatrix.x4)
            #pragma unroll
            for (int np = 0; np < 2; ++np) {
                const int r  = wn * 32 + np * 16 + ((sub >> 1) << 3) + l7;
                const int ch = ks * 2 + (sub & 1);
                uint32_t t[4];
                LDSM_X4(t, sb + OFF_BH + (uint32_t)(r * 128 + ((ch ^ (r & 7)) << 4)));
                bf[np*2][0]   = t[0]; bf[np*2][1]   = t[1];
                bf[np*2+1][0] = t[2]; bf[np*2+1][1] = t[3];
            }
            // pass 1+2: Ah*Bh, Al*Bh
            #pragma unroll
            for (int mt = 0; mt < 4; ++mt)
                #pragma unroll
                for (int nt = 0; nt < 4; ++nt) {
                    MMA_BF16(acc[mt][nt], ah[mt], bf[nt]);
                    MMA_BF16(acc[mt][nt], al[mt], bf[nt]);
                }
            // B lo fragments (overwrite bf)
            #pragma unroll
            for (int np = 0; np < 2; ++np) {
                const int r  = wn * 32 + np * 16 + ((sub >> 1) << 3) + l7;
                const int ch = ks * 2 + (sub & 1);
                uint32_t t[4];
                LDSM_X4(t, sb + OFF_BL + (uint32_t)(r * 128 + ((ch ^ (r & 7)) << 4)));
                bf[np*2][0]   = t[0]; bf[np*2][1]   = t[1];
                bf[np*2+1][0] = t[2]; bf[np*2+1][1] = t[3];
            }
            // pass 3: Ah*Bl
            #pragma unroll
            for (int mt = 0; mt < 4; ++mt)
                #pragma unroll
                for (int nt = 0; nt < 4; ++nt)
                    MMA_BF16(acc[mt][nt], ah[mt], bf[nt]);
        }
    }

    // epilogue
    const int er = lane >> 2;
    const int ec = (lane & 3) * 2;
    #pragma unroll
    for (int mt = 0; mt < 4; ++mt) {
        const int grow = row0 + wm * 64 + mt * 16 + er;
        #pragma unroll
        for (int nt = 0; nt < 4; ++nt) {
            const int gcol = col0 + wn * 32 + nt * 8 + ec;
            float bx = 0.f, by = 0.f;
            if (bias) { bx = bias[gcol]; by = bias[gcol + 1]; }
            float2 v0 = make_float2(acc[mt][nt][0] + bx, acc[mt][nt][1] + by);
            float2 v1 = make_float2(acc[mt][nt][2] + bx, acc[mt][nt][3] + by);
            *(float2*)&C[(size_t)grow * ldc + gcol] = v0;
            *(float2*)&C[(size_t)(grow + 8) * ldc + gcol] = v1;
        }
    }
}

// ---------------- Flash attention (fp32, exact online softmax) ----------------
#define AT_BM 128
#define AT_BN 64
#define AT_SMEM (AT_BN * 16 * 16 * 2 + AT_BM * 65 * 4)

__global__ __launch_bounds__(AT_BM)
void attn_kernel(const float* __restrict__ Q, const float* __restrict__ K,
                 const float* __restrict__ V, float* __restrict__ O)
{
    extern __shared__ __align__(16) char smem_raw[];
    float4* Ks = (float4*)smem_raw;                       // [AT_BN][16]
    float4* Vs = Ks + AT_BN * 16;                         // [AT_BN][16]
    float*  Ss = (float*)(Vs + AT_BN * 16);               // [AT_BM][65]

    const int tid = threadIdx.x;
    const int h = blockIdx.y;
    const int b = blockIdx.z;
    const int qrow = blockIdx.x * AT_BM + tid;

    const size_t base = ((size_t)b * T_SZ) * DM + h * HD;

    float q[HD];
    {
        const float4* qg = (const float4*)(Q + base + (size_t)qrow * DM);
        #pragma unroll
        for (int d = 0; d < 16; ++d) {
            float4 v = qg[d];
            q[4*d+0] = v.x; q[4*d+1] = v.y; q[4*d+2] = v.z; q[4*d+3] = v.w;
        }
    }

    float acc[HD];
    #pragma unroll
    for (int d = 0; d < HD; ++d) acc[d] = 0.f;
    float m = -1e30f;
    float l = 0.f;

    const int n_tiles = T_SZ / AT_BN;
    for (int kt = 0; kt < n_tiles; ++kt) {
        __syncthreads();
        {
            const int krow0 = kt * AT_BN;
            #pragma unroll
            for (int i = 0; i < (AT_BN * 16) / AT_BM; ++i) {
                int idx = tid + i * AT_BM;
                int r = idx >> 4;
                int c = idx & 15;
                const float4* kg = (const float4*)(K + base + (size_t)(krow0 + r) * DM);
                const float4* vg = (const float4*)(V + base + (size_t)(krow0 + r) * DM);
                Ks[r * 16 + c] = kg[c];
                Vs[r * 16 + c] = vg[c];
            }
        }
        __syncthreads();

        // pass 1: scores + running max (4 independent accumulators for ILP)
        float mt = m;
        #pragma unroll 4
        for (int j = 0; j < AT_BN; ++j) {
            float s0 = 0.f, s1 = 0.f, s2 = 0.f, s3 = 0.f;
            #pragma unroll
            for (int d = 0; d < 16; ++d) {
                float4 kk = Ks[j * 16 + d];
                s0 += q[4*d+0] * kk.x;
                s1 += q[4*d+1] * kk.y;
                s2 += q[4*d+2] * kk.z;
                s3 += q[4*d+3] * kk.w;
            }
            float s = ((s0 + s1) + (s2 + s3)) * 0.125f;
            Ss[tid * 65 + j] = s;
            mt = fmaxf(mt, s);
        }

        float corr = __expf(m - mt);
        l *= corr;
        #pragma unroll
        for (int d = 0; d < HD; ++d) acc[d] *= corr;

        for (int j = 0; j < AT_BN; ++j) {
            float p = __expf(Ss[tid * 65 + j] - mt);
            l += p;
            #pragma unroll
            for (int d = 0; d < 16; ++d) {
                float4 vv = Vs[j * 16 + d];
                acc[4*d+0] += p * vv.x;
                acc[4*d+1] += p * vv.y;
                acc[4*d+2] += p * vv.z;
                acc[4*d+3] += p * vv.w;
            }
        }
        m = mt;
    }

    float inv = 1.f / (l + 1e-8f);
    float4* og = (float4*)(O + base + (size_t)qrow * DM);
    #pragma unroll
    for (int d = 0; d < 16; ++d) {
        float4 o;
        o.x = acc[4*d+0] * inv;
        o.y = acc[4*d+1] * inv;
        o.z = acc[4*d+2] * inv;
        o.w = acc[4*d+3] * inv;
        og[d] = o;
    }
}

// ---------------- launch ----------------
extern "C" void kernel_launch(void* const* d_in, const int* in_sizes, int n_in,
                              void* d_out, int out_size)
{
    const float* x  = (const float*)d_in[0];
    const float* Wq = (const float*)d_in[1];
    const float* Wk = (const float*)d_in[2];
    const float* Wv = (const float*)d_in[3];
    const float* Wo = (const float*)d_in[4];
    const float* bo = (const float*)d_in[5];
    float* out = (float*)d_out;

    float *qb, *kb, *vb, *ob;
    cudaGetSymbolAddress((void**)&qb, g_Q);
    cudaGetSymbolAddress((void**)&kb, g_K);
    cudaGetSymbolAddress((void**)&vb, g_V);
    cudaGetSymbolAddress((void**)&ob, g_O);

    __nv_bfloat16 *xh, *xl, *oh, *ol;
    __nv_bfloat16 *wqh, *wql, *wkh, *wkl, *wvh, *wvl, *woh, *wol;
    cudaGetSymbolAddress((void**)&xh, g_xh);
    cudaGetSymbolAddress((void**)&xl, g_xl);
    cudaGetSymbolAddress((void**)&oh, g_oh);
    cudaGetSymbolAddress((void**)&ol, g_ol);
    cudaGetSymbolAddress((void**)&wqh, g_wqh);
    cudaGetSymbolAddress((void**)&wql, g_wql);
    cudaGetSymbolAddress((void**)&wkh, g_wkh);
    cudaGetSymbolAddress((void**)&wkl, g_wkl);
    cudaGetSymbolAddress((void**)&wvh, g_wvh);
    cudaGetSymbolAddress((void**)&wvl, g_wvl);
    cudaGetSymbolAddress((void**)&woh, g_woh);
    cudaGetSymbolAddress((void**)&wol, g_wol);

    cudaFuncSetAttribute(attn_kernel, cudaFuncAttributeMaxDynamicSharedMemorySize, AT_SMEM);
    cudaFuncSetAttribute(gemm_mma_kernel, cudaFuncAttributeMaxDynamicSharedMemorySize, GEMM_SMEM);

    // split inputs + weights to bf16 hi/lo
    const int n4x = NELEM / 4;
    const int n4w = (DM * DM) / 4;
    split_kernel<<<n4x / 256, 256>>>(x, xh, xl, n4x);
    split_kernel<<<n4w / 256, 256>>>(Wq, wqh, wql, n4w);
    split_kernel<<<n4w / 256, 256>>>(Wk, wkh, wkl, n4w);
    split_kernel<<<n4w / 256, 256>>>(Wv, wvh, wvl, n4w);
    split_kernel<<<n4w / 256, 256>>>(Wo, woh, wol, n4w);

    // Q/K/V projections on tensor cores (HMMA)
    dim3 ggrid(DM / GBN, MROWS / GBM);   // (8, 64)
    gemm_mma_kernel<<<ggrid, 256, GEMM_SMEM>>>(xh, xl, wqh, wql, qb, nullptr, DM, DM);
    gemm_mma_kernel<<<ggrid, 256, GEMM_SMEM>>>(xh, xl, wkh, wkl, kb, nullptr, DM, DM);
    gemm_mma_kernel<<<ggrid, 256, GEMM_SMEM>>>(xh, xl, wvh, wvl, vb, nullptr, DM, DM);

    // attention (fp32)
    dim3 agrid(T_SZ / AT_BM, NH, B_SZ);  // (16, 16, 4)
    attn_kernel<<<agrid, AT_BM, AT_SMEM>>>(qb, kb, vb, ob);

    // output projection (+bias) on tensor cores
    split_kernel<<<n4x / 256, 256>>>(ob, oh, ol, n4x);
    gemm_mma_kernel<<<ggrid, 256, GEMM_SMEM>>>(oh, ol, woh, wol, out, bo, DM, DM);
}

// round 11
// speedup vs baseline: 1.9384x; 1.5236x over previous
#include <cuda_runtime.h>
#include <cuda_bf16.h>
#include <cstdint>
#include <math.h>

// Problem constants
#define B_SZ 4
#define T_SZ 2048
#define DM   1024
#define NH   16
#define HD   64
#define MROWS (B_SZ * T_SZ)   // 8192
#define NELEM (MROWS * DM)

// ---------------- scratch (allocation-free) ----------------
__device__ float g_Q[NELEM];
__device__ float g_K[NELEM];
__device__ float g_V[NELEM];
__device__ float g_O[NELEM];

__device__ __nv_bfloat16 g_xh[NELEM];
__device__ __nv_bfloat16 g_xl[NELEM];
__device__ __nv_bfloat16 g_oh[NELEM];
__device__ __nv_bfloat16 g_ol[NELEM];
__device__ __nv_bfloat16 g_qh[NELEM];
__device__ __nv_bfloat16 g_ql[NELEM];
__device__ __nv_bfloat16 g_kh[NELEM];
__device__ __nv_bfloat16 g_kl[NELEM];
__device__ __nv_bfloat16 g_vh[NELEM];
__device__ __nv_bfloat16 g_vl[NELEM];
__device__ __nv_bfloat16 g_wqh[DM * DM];
__device__ __nv_bfloat16 g_wql[DM * DM];
__device__ __nv_bfloat16 g_wkh[DM * DM];
__device__ __nv_bfloat16 g_wkl[DM * DM];
__device__ __nv_bfloat16 g_wvh[DM * DM];
__device__ __nv_bfloat16 g_wvl[DM * DM];
__device__ __nv_bfloat16 g_woh[DM * DM];
__device__ __nv_bfloat16 g_wol[DM * DM];

// ---------------- helpers ----------------
__device__ __forceinline__ uint32_t smem_u32(const void* p) {
    uint32_t a;
    asm("{ .reg .u64 t; cvta.to.shared.u64 t, %1; cvt.u32.u64 %0, t; }" : "=r"(a) : "l"(p));
    return a;
}

#define LDSM_X4(r, addr) \
    asm volatile("ldmatrix.sync.aligned.m8n8.x4.shared.b16 {%0,%1,%2,%3}, [%4];" \
        : "=r"((r)[0]), "=r"((r)[1]), "=r"((r)[2]), "=r"((r)[3]) : "r"(addr))

#define LDSM_X4_T(r, addr) \
    asm volatile("ldmatrix.sync.aligned.m8n8.x4.trans.shared.b16 {%0,%1,%2,%3}, [%4];" \
        : "=r"((r)[0]), "=r"((r)[1]), "=r"((r)[2]), "=r"((r)[3]) : "r"(addr))

// D += A*B  (m16n8k16, bf16 in, fp32 accum)
#define MMA_BF16(d, a, b0, b1) \
    asm volatile("mma.sync.aligned.m16n8k16.row.col.f32.bf16.bf16.f32 " \
        "{%0,%1,%2,%3}, {%4,%5,%6,%7}, {%8,%9}, {%0,%1,%2,%3};" \
        : "+f"((d)[0]), "+f"((d)[1]), "+f"((d)[2]), "+f"((d)[3]) \
        : "r"((a)[0]), "r"((a)[1]), "r"((a)[2]), "r"((a)[3]), "r"(b0), "r"(b1))

// split-pack two fp32 into bf16x2 hi + bf16x2 lo (a -> low half, b -> high half)
__device__ __forceinline__ void split_pack2(float a, float b, uint32_t& hi, uint32_t& lo) {
    __nv_bfloat16 ha = __float2bfloat16(a);
    __nv_bfloat16 hb = __float2bfloat16(b);
    __nv_bfloat16 la = __float2bfloat16(a - __bfloat162float(ha));
    __nv_bfloat16 lb = __float2bfloat16(b - __bfloat162float(hb));
    __nv_bfloat162 vh(ha, hb), vl(la, lb);
    hi = *(uint32_t*)&vh;
    lo = *(uint32_t*)&vl;
}

// ---------------- split fp32 -> bf16 hi/lo (with scale) ----------------
__global__ __launch_bounds__(256)
void split_kernel(const float* __restrict__ src, __nv_bfloat16* __restrict__ hi,
                  __nv_bfloat16* __restrict__ lo, int n4, float scale)
{
    int i = blockIdx.x * blockDim.x + threadIdx.x;
    if (i >= n4) return;
    float4 v = ((const float4*)src)[i];
    v.x *= scale; v.y *= scale; v.z *= scale; v.w *= scale;
    __nv_bfloat16 h0 = __float2bfloat16(v.x);
    __nv_bfloat16 h1 = __float2bfloat16(v.y);
    __nv_bfloat16 h2 = __float2bfloat16(v.z);
    __nv_bfloat16 h3 = __float2bfloat16(v.w);
    __nv_bfloat16 l0 = __float2bfloat16(v.x - __bfloat162float(h0));
    __nv_bfloat16 l1 = __float2bfloat16(v.y - __bfloat162float(h1));
    __nv_bfloat16 l2 = __float2bfloat16(v.z - __bfloat162float(h2));
    __nv_bfloat16 l3 = __float2bfloat16(v.w - __bfloat162float(h3));
    ((__nv_bfloat162*)hi)[2*i]   = __nv_bfloat162(h0, h1);
    ((__nv_bfloat162*)hi)[2*i+1] = __nv_bfloat162(h2, h3);
    ((__nv_bfloat162*)lo)[2*i]   = __nv_bfloat162(l0, l1);
    ((__nv_bfloat162*)lo)[2*i+1] = __nv_bfloat162(l2, l3);
}

// ---------------- mma.sync split-bf16 NT GEMM (validated in R6) ----------------
#define GBM 128
#define GBN 128
#define GBK 64
#define OP_BYTES (GBM * GBK * 2)
#define OFF_AH 0
#define OFF_AL (OP_BYTES)
#define OFF_BH (2 * OP_BYTES)
#define OFF_BL (3 * OP_BYTES)
#define GEMM_SMEM (4 * OP_BYTES)      // 65536

__global__ __launch_bounds__(256)
void gemm_mma_kernel(const __nv_bfloat16* __restrict__ Ah, const __nv_bfloat16* __restrict__ Al,
                     const __nv_bfloat16* __restrict__ Bh, const __nv_bfloat16* __restrict__ Bl,
                     float* __restrict__ C, const float* __restrict__ bias, int Kdim, int ldc)
{
    extern __shared__ __align__(128) char smem[];
    const uint32_t sb = smem_u32(smem);

    const int tid  = threadIdx.x;
    const int warp = tid >> 5;
    const int lane = tid & 31;
    const int wm = warp & 1;
    const int wn = warp >> 1;
    const int row0 = blockIdx.y * GBM;
    const int col0 = blockIdx.x * GBN;

    float acc[4][4][4];
    #pragma unroll
    for (int a = 0; a < 4; ++a)
        #pragma unroll
        for (int b = 0; b < 4; ++b)
            #pragma unroll
            for (int c = 0; c < 4; ++c) acc[a][b][c] = 0.f;

    const int sub = lane >> 3;
    const int l7  = lane & 7;

    const int nchunk = Kdim / GBK;
    for (int kc = 0; kc < nchunk; ++kc) {
        if (kc) __syncthreads();
        {
            const int cc = tid & 7;
            #pragma unroll
            for (int i = 0; i < 4; ++i) {
                const int rr = (tid >> 3) + i * 32;
                const uint32_t so = (uint32_t)(rr * 128 + ((cc ^ (rr & 7)) << 4));
                const size_t ga = (size_t)(row0 + rr) * Kdim + kc * GBK + cc * 8;
                const size_t gb = (size_t)(col0 + rr) * Kdim + kc * GBK + cc * 8;
                *(uint4*)(smem + OFF_AH + so) = *(const uint4*)(Ah + ga);
                *(uint4*)(smem + OFF_AL + so) = *(const uint4*)(Al + ga);
                *(uint4*)(smem + OFF_BH + so) = *(const uint4*)(Bh + gb);
                *(uint4*)(smem + OFF_BL + so) = *(const uint4*)(Bl + gb);
            }
        }
        __syncthreads();

        #pragma unroll
        for (int ks = 0; ks < 4; ++ks) {
            uint32_t ah[4][4], al[4][4], bf[4][2];
            #pragma unroll
            for (int mt = 0; mt < 4; ++mt) {
                const int r  = wm * 64 + mt * 16 + ((sub & 1) << 3) + l7;
                const int ch = ks * 2 + (sub >> 1);
                const uint32_t ad = sb + (uint32_t)(r * 128 + ((ch ^ (r & 7)) << 4));
                LDSM_X4(ah[mt], ad + OFF_AH);
                LDSM_X4(al[mt], ad + OFF_AL);
            }
            #pragma unroll
            for (int np = 0; np < 2; ++np) {
                const int r  = wn * 32 + np * 16 + ((sub >> 1) << 3) + l7;
                const int ch = ks * 2 + (sub & 1);
                uint32_t t[4];
                LDSM_X4(t, sb + OFF_BH + (uint32_t)(r * 128 + ((ch ^ (r & 7)) << 4)));
                bf[np*2][0]   = t[0]; bf[np*2][1]   = t[1];
                bf[np*2+1][0] = t[2]; bf[np*2+1][1] = t[3];
            }
            #pragma unroll
            for (int mt = 0; mt < 4; ++mt)
                #pragma unroll
                for (int nt = 0; nt < 4; ++nt) {
                    MMA_BF16(acc[mt][nt], ah[mt], bf[nt][0], bf[nt][1]);
                    MMA_BF16(acc[mt][nt], al[mt], bf[nt][0], bf[nt][1]);
                }
            #pragma unroll
            for (int np = 0; np < 2; ++np) {
                const int r  = wn * 32 + np * 16 + ((sub >> 1) << 3) + l7;
                const int ch = ks * 2 + (sub & 1);
                uint32_t t[4];
                LDSM_X4(t, sb + OFF_BL + (uint32_t)(r * 128 + ((ch ^ (r & 7)) << 4)));
                bf[np*2][0]   = t[0]; bf[np*2][1]   = t[1];
                bf[np*2+1][0] = t[2]; bf[np*2+1][1] = t[3];
            }
            #pragma unroll
            for (int mt = 0; mt < 4; ++mt)
                #pragma unroll
                for (int nt = 0; nt < 4; ++nt)
                    MMA_BF16(acc[mt][nt], ah[mt], bf[nt][0], bf[nt][1]);
        }
    }

    const int er = lane >> 2;
    const int ec = (lane & 3) * 2;
    #pragma unroll
    for (int mt = 0; mt < 4; ++mt) {
        const int grow = row0 + wm * 64 + mt * 16 + er;
        #pragma unroll
        for (int nt = 0; nt < 4; ++nt) {
            const int gcol = col0 + wn * 32 + nt * 8 + ec;
            float bx = 0.f, by = 0.f;
            if (bias) { bx = bias[gcol]; by = bias[gcol + 1]; }
            float2 v0 = make_float2(acc[mt][nt][0] + bx, acc[mt][nt][1] + by);
            float2 v1 = make_float2(acc[mt][nt][2] + bx, acc[mt][nt][3] + by);
            *(float2*)&C[(size_t)grow * ldc + gcol] = v0;
            *(float2*)&C[(size_t)(grow + 8) * ldc + gcol] = v1;
        }
    }
}

// ---------------- HMMA flash attention (split bf16 on BOTH GEMMs) ----------------
// Grid (T/128, NH, B), 256 thr (8 warps). Warp w owns q rows [16w,16w+16).
// S = Qh*Kh + Qh*Kl + Ql*Kh;  PV = Ph*Vh + Ph*Vl + Pl*Vh.
#define FA_BN 64
#define FA_TILEB (FA_BN * 128)      // 8192 bytes per operand tile
#define FA_SMEM (4 * FA_TILEB)      // Kh | Kl | Vh | Vl  (Q staged through first two)

__global__ __launch_bounds__(256)
void attn_mma_kernel(const __nv_bfloat16* __restrict__ Qh, const __nv_bfloat16* __restrict__ Ql,
                     const __nv_bfloat16* __restrict__ Kh, const __nv_bfloat16* __restrict__ Kl,
                     const __nv_bfloat16* __restrict__ Vh, const __nv_bfloat16* __restrict__ Vl,
                     float* __restrict__ O)
{
    __shared__ __align__(128) char sm[FA_SMEM];
    const uint32_t sb = smem_u32(sm);

    const int tid  = threadIdx.x;
    const int warp = tid >> 5;
    const int lane = tid & 31;
    const int sub  = lane >> 3;
    const int l7   = lane & 7;
    const int h = blockIdx.y;
    const int b = blockIdx.z;
    const int q0 = blockIdx.x * 128;

    const size_t rowbase = (size_t)b * T_SZ;
    const int    colbase = h * HD;

    // ---- stage Q (128 rows x 64 bf16) and keep A fragments (hi then lo)
    uint32_t qfh[4][4], qfl[4][4];
    #pragma unroll
    for (int pass = 0; pass < 2; ++pass) {
        const __nv_bfloat16* src = pass ? Ql : Qh;
        if (pass) __syncthreads();
        #pragma unroll
        for (int i = 0; i < 4; ++i) {
            int u = tid + i * 256;
            int r = u >> 3, c = u & 7;
            const uint4 v = *(const uint4*)(src + (rowbase + q0 + r) * DM + colbase + c * 8);
            *(uint4*)(sm + r * 128 + ((c ^ (r & 7)) << 4)) = v;
        }
        __syncthreads();
        #pragma unroll
        for (int t = 0; t < 4; ++t) {
            const int r  = warp * 16 + ((sub & 1) << 3) + l7;
            const int ch = t * 2 + (sub >> 1);
            const uint32_t ad = sb + (uint32_t)(r * 128 + ((ch ^ (r & 7)) << 4));
            if (pass) { LDSM_X4(qfl[t], ad); } else { LDSM_X4(qfh[t], ad); }
        }
    }

    float acc[8][4];
    #pragma unroll
    for (int j = 0; j < 8; ++j)
        #pragma unroll
        for (int c = 0; c < 4; ++c) acc[j][c] = 0.f;
    float m0 = -1e30f, m1 = -1e30f, l0 = 0.f, l1 = 0.f;

    for (int kt = 0; kt < T_SZ / FA_BN; ++kt) {
        __syncthreads();
        // load Kh/Kl/Vh/Vl tiles (64 rows x 128B each)
        {
            const int key0 = kt * FA_BN;
            #pragma unroll
            for (int i = 0; i < 2; ++i) {
                int u = tid + i * 256;
                int r = u >> 3, c = u & 7;
                const size_t g = (rowbase + key0 + r) * DM + colbase + c * 8;
                const uint32_t so = (uint32_t)(r * 128 + ((c ^ (r & 7)) << 4));
                *(uint4*)(sm + so)                = *(const uint4*)(Kh + g);
                *(uint4*)(sm + FA_TILEB + so)     = *(const uint4*)(Kl + g);
                *(uint4*)(sm + 2 * FA_TILEB + so) = *(const uint4*)(Vh + g);
                *(uint4*)(sm + 3 * FA_TILEB + so) = *(const uint4*)(Vl + g);
            }
        }
        __syncthreads();

        // ---- S = Q K^T  (split: QhKh + QhKl + QlKh)
        float st[8][4];
        #pragma unroll
        for (int j = 0; j < 8; ++j)
            #pragma unroll
            for (int c = 0; c < 4; ++c) st[j][c] = 0.f;

        #pragma unroll
        for (int np = 0; np < 4; ++np) {
            #pragma unroll
            for (int t = 0; t < 4; ++t) {
                const int r  = np * 16 + ((sub >> 1) << 3) + l7;
                const int ch = t * 2 + (sub & 1);
                const uint32_t so = (uint32_t)(r * 128 + ((ch ^ (r & 7)) << 4));
                uint32_t eh[4], el[4];
                LDSM_X4(eh, sb + so);
                LDSM_X4(el, sb + FA_TILEB + so);
                MMA_BF16(st[np*2],   qfh[t], eh[0], eh[1]);
                MMA_BF16(st[np*2+1], qfh[t], eh[2], eh[3]);
                MMA_BF16(st[np*2],   qfh[t], el[0], el[1]);
                MMA_BF16(st[np*2+1], qfh[t], el[2], el[3]);
                MMA_BF16(st[np*2],   qfl[t], eh[0], eh[1]);
                MMA_BF16(st[np*2+1], qfl[t], eh[2], eh[3]);
            }
        }

        // ---- online softmax (log2 domain; Q pre-scaled by 0.125*log2e)
        float tm0 = st[0][0], tm1 = st[0][2];
        #pragma unroll
        for (int j = 0; j < 8; ++j) {
            tm0 = fmaxf(tm0, fmaxf(st[j][0], st[j][1]));
            tm1 = fmaxf(tm1, fmaxf(st[j][2], st[j][3]));
        }
        tm0 = fmaxf(tm0, __shfl_xor_sync(0xffffffffu, tm0, 1));
        tm0 = fmaxf(tm0, __shfl_xor_sync(0xffffffffu, tm0, 2));
        tm1 = fmaxf(tm1, __shfl_xor_sync(0xffffffffu, tm1, 1));
        tm1 = fmaxf(tm1, __shfl_xor_sync(0xffffffffu, tm1, 2));
        const float nm0 = fmaxf(m0, tm0), nm1 = fmaxf(m1, tm1);
        const float c0 = exp2f(m0 - nm0), c1 = exp2f(m1 - nm1);
        m0 = nm0; m1 = nm1;
        l0 *= c0; l1 *= c1;
        #pragma unroll
        for (int j = 0; j < 8; ++j) {
            acc[j][0] *= c0; acc[j][1] *= c0;
            acc[j][2] *= c1; acc[j][3] *= c1;
        }
        #pragma unroll
        for (int j = 0; j < 8; ++j) {
            st[j][0] = exp2f(st[j][0] - m0);
            st[j][1] = exp2f(st[j][1] - m0);
            st[j][2] = exp2f(st[j][2] - m1);
            st[j][3] = exp2f(st[j][3] - m1);
            l0 += st[j][0] + st[j][1];
            l1 += st[j][2] + st[j][3];
        }

        // ---- split-pack P into hi/lo A fragments (k = keys)
        uint32_t pfh[4][4], pfl[4][4];
        #pragma unroll
        for (int t = 0; t < 4; ++t) {
            split_pack2(st[2*t][0],   st[2*t][1],   pfh[t][0], pfl[t][0]);
            split_pack2(st[2*t][2],   st[2*t][3],   pfh[t][1], pfl[t][1]);
            split_pack2(st[2*t+1][0], st[2*t+1][1], pfh[t][2], pfl[t][2]);
            split_pack2(st[2*t+1][2], st[2*t+1][3], pfh[t][3], pfl[t][3]);
        }

        // ---- acc += P V   (split: PhVh + PhVl + PlVh; V via ldmatrix.trans)
        #pragma unroll
        for (int t = 0; t < 4; ++t) {             // key chunks of 16
            #pragma unroll
            for (int dp = 0; dp < 4; ++dp) {      // dim pairs of 16
                const int r  = t * 16 + ((sub & 1) << 3) + l7;
                const int ch = dp * 2 + (sub >> 1);
                const uint32_t so = (uint32_t)(r * 128 + ((ch ^ (r & 7)) << 4));
                uint32_t vh[4], vl[4];
                LDSM_X4_T(vh, sb + 2 * FA_TILEB + so);
                LDSM_X4_T(vl, sb + 3 * FA_TILEB + so);
                MMA_BF16(acc[dp*2],   pfh[t], vh[0], vh[1]);
                MMA_BF16(acc[dp*2+1], pfh[t], vh[2], vh[3]);
                MMA_BF16(acc[dp*2],   pfh[t], vl[0], vl[1]);
                MMA_BF16(acc[dp*2+1], pfh[t], vl[2], vl[3]);
                MMA_BF16(acc[dp*2],   pfl[t], vh[0], vh[1]);
                MMA_BF16(acc[dp*2+1], pfl[t], vh[2], vh[3]);
            }
        }
    }

    // ---- finalize
    l0 += __shfl_xor_sync(0xffffffffu, l0, 1);
    l0 += __shfl_xor_sync(0xffffffffu, l0, 2);
    l1 += __shfl_xor_sync(0xffffffffu, l1, 1);
    l1 += __shfl_xor_sync(0xffffffffu, l1, 2);
    const float inv0 = 1.f / (l0 + 1e-8f);
    const float inv1 = 1.f / (l1 + 1e-8f);

    const int r0 = q0 + warp * 16 + (lane >> 2);
    const int ec = (lane & 3) * 2;
    #pragma unroll
    for (int j = 0; j < 8; ++j) {
        const int gcol = colbase + j * 8 + ec;
        *(float2*)&O[(rowbase + r0) * DM + gcol] =
            make_float2(acc[j][0] * inv0, acc[j][1] * inv0);
        *(float2*)&O[(rowbase + r0 + 8) * DM + gcol] =
            make_float2(acc[j][2] * inv1, acc[j][3] * inv1);
    }
}

// ---------------- launch ----------------
extern "C" void kernel_launch(void* const* d_in, const int* in_sizes, int n_in,
                              void* d_out, int out_size)
{
    const float* x  = (const float*)d_in[0];
    const float* Wq = (const float*)d_in[1];
    const float* Wk = (const float*)d_in[2];
    const float* Wv = (const float*)d_in[3];
    const float* Wo = (const float*)d_in[4];
    const float* bo = (const float*)d_in[5];
    float* out = (float*)d_out;

    float *qb, *kb, *vb, *ob;
    cudaGetSymbolAddress((void**)&qb, g_Q);
    cudaGetSymbolAddress((void**)&kb, g_K);
    cudaGetSymbolAddress((void**)&vb, g_V);
    cudaGetSymbolAddress((void**)&ob, g_O);

    __nv_bfloat16 *xh, *xl, *oh, *ol, *qh, *ql, *kh, *kl, *vh, *vl;
    __nv_bfloat16 *wqh, *wql, *wkh, *wkl, *wvh, *wvl, *woh, *wol;
    cudaGetSymbolAddress((void**)&xh, g_xh);
    cudaGetSymbolAddress((void**)&xl, g_xl);
    cudaGetSymbolAddress((void**)&oh, g_oh);
    cudaGetSymbolAddress((void**)&ol, g_ol);
    cudaGetSymbolAddress((void**)&qh, g_qh);
    cudaGetSymbolAddress((void**)&ql, g_ql);
    cudaGetSymbolAddress((void**)&kh, g_kh);
    cudaGetSymbolAddress((void**)&kl, g_kl);
    cudaGetSymbolAddress((void**)&vh, g_vh);
    cudaGetSymbolAddress((void**)&vl, g_vl);
    cudaGetSymbolAddress((void**)&wqh, g_wqh);
    cudaGetSymbolAddress((void**)&wql, g_wql);
    cudaGetSymbolAddress((void**)&wkh, g_wkh);
    cudaGetSymbolAddress((void**)&wkl, g_wkl);
    cudaGetSymbolAddress((void**)&wvh, g_wvh);
    cudaGetSymbolAddress((void**)&wvl, g_wvl);
    cudaGetSymbolAddress((void**)&woh, g_woh);
    cudaGetSymbolAddress((void**)&wol, g_wol);

    cudaFuncSetAttribute(gemm_mma_kernel, cudaFuncAttributeMaxDynamicSharedMemorySize, GEMM_SMEM);

    const int n4x = NELEM / 4;
    const int n4w = (DM * DM) / 4;
    split_kernel<<<n4x / 256, 256>>>(x, xh, xl, n4x, 1.0f);
    split_kernel<<<n4w / 256, 256>>>(Wq, wqh, wql, n4w, 1.0f);
    split_kernel<<<n4w / 256, 256>>>(Wk, wkh, wkl, n4w, 1.0f);
    split_kernel<<<n4w / 256, 256>>>(Wv, wvh, wvl, n4w, 1.0f);
    split_kernel<<<n4w / 256, 256>>>(Wo, woh, wol, n4w, 1.0f);

    dim3 ggrid(DM / GBN, MROWS / GBM);   // (8, 64)
    gemm_mma_kernel<<<ggrid, 256, GEMM_SMEM>>>(xh, xl, wqh, wql, qb, nullptr, DM, DM);
    gemm_mma_kernel<<<ggrid, 256, GEMM_SMEM>>>(xh, xl, wkh, wkl, kb, nullptr, DM, DM);
    gemm_mma_kernel<<<ggrid, 256, GEMM_SMEM>>>(xh, xl, wvh, wvl, vb, nullptr, DM, DM);

    // split Q (scaled into log2-softmax domain), K, V to bf16 hi/lo
    const float qscale = 0.125f * 1.44269504088896341f;   // (1/sqrt(64)) * log2(e)
    split_kernel<<<n4x / 256, 256>>>(qb, qh, ql, n4x, qscale);
    split_kernel<<<n4x / 256, 256>>>(kb, kh, kl, n4x, 1.0f);
    split_kernel<<<n4x / 256, 256>>>(vb, vh, vl, n4x, 1.0f);

    dim3 agrid(T_SZ / 128, NH, B_SZ);    // (16, 16, 4)
    attn_mma_kernel<<<agrid, 256>>>(qh, ql, kh, kl, vh, vl, ob);

    split_kernel<<<n4x / 256, 256>>>(ob, oh, ol, n4x, 1.0f);
    gemm_mma_kernel<<<ggrid, 256, GEMM_SMEM>>>(oh, ol, woh, wol, out, bo, DM, DM);
}

// round 12
// speedup vs baseline: 3.7309x; 1.9247x over previous
#include <cuda_runtime.h>
#include <cuda_bf16.h>
#include <cstdint>
#include <math.h>

// Problem constants
#define B_SZ 4
#define T_SZ 2048
#define DM   1024
#define NH   16
#define HD   64
#define MROWS (B_SZ * T_SZ)   // 8192
#define NELEM (MROWS * DM)

// ---------------- scratch (allocation-free) ----------------
__device__ __nv_bfloat16 g_xh[NELEM];
__device__ __nv_bfloat16 g_xl[NELEM];
__device__ __nv_bfloat16 g_oh[NELEM];
__device__ __nv_bfloat16 g_ol[NELEM];
__device__ __nv_bfloat16 g_qh[NELEM];
__device__ __nv_bfloat16 g_ql[NELEM];
__device__ __nv_bfloat16 g_kh[NELEM];
__device__ __nv_bfloat16 g_kl[NELEM];
__device__ __nv_bfloat16 g_vh[NELEM];
__device__ __nv_bfloat16 g_vl[NELEM];
__device__ __nv_bfloat16 g_wqh[DM * DM];
__device__ __nv_bfloat16 g_wql[DM * DM];
__device__ __nv_bfloat16 g_wkh[DM * DM];
__device__ __nv_bfloat16 g_wkl[DM * DM];
__device__ __nv_bfloat16 g_wvh[DM * DM];
__device__ __nv_bfloat16 g_wvl[DM * DM];
__device__ __nv_bfloat16 g_woh[DM * DM];
__device__ __nv_bfloat16 g_wol[DM * DM];

// ---------------- helpers ----------------
__device__ __forceinline__ uint32_t smem_u32(const void* p) {
    uint32_t a;
    asm("{ .reg .u64 t; cvta.to.shared.u64 t, %1; cvt.u32.u64 %0, t; }" : "=r"(a) : "l"(p));
    return a;
}

#define LDSM_X4(r, addr) \
    asm volatile("ldmatrix.sync.aligned.m8n8.x4.shared.b16 {%0,%1,%2,%3}, [%4];" \
        : "=r"((r)[0]), "=r"((r)[1]), "=r"((r)[2]), "=r"((r)[3]) : "r"(addr))

#define LDSM_X4_T(r, addr) \
    asm volatile("ldmatrix.sync.aligned.m8n8.x4.trans.shared.b16 {%0,%1,%2,%3}, [%4];" \
        : "=r"((r)[0]), "=r"((r)[1]), "=r"((r)[2]), "=r"((r)[3]) : "r"(addr))

#define MMA_BF16(d, a, b0, b1) \
    asm volatile("mma.sync.aligned.m16n8k16.row.col.f32.bf16.bf16.f32 " \
        "{%0,%1,%2,%3}, {%4,%5,%6,%7}, {%8,%9}, {%0,%1,%2,%3};" \
        : "+f"((d)[0]), "+f"((d)[1]), "+f"((d)[2]), "+f"((d)[3]) \
        : "r"((a)[0]), "r"((a)[1]), "r"((a)[2]), "r"((a)[3]), "r"(b0), "r"(b1))

#define CP_ASYNC16(saddr, gptr) \
    asm volatile("cp.async.cg.shared.global [%0], [%1], 16;" :: "r"(saddr), "l"(gptr))
#define CP_COMMIT() asm volatile("cp.async.commit_group;" ::: "memory")
#define CP_WAIT0()  asm volatile("cp.async.wait_group 0;" ::: "memory")
#define CP_WAIT1()  asm volatile("cp.async.wait_group 1;" ::: "memory")

// split-pack two fp32 into bf16x2 hi + bf16x2 lo
__device__ __forceinline__ void split_pack2(float a, float b, uint32_t& hi, uint32_t& lo) {
    __nv_bfloat16 ha = __float2bfloat16(a);
    __nv_bfloat16 hb = __float2bfloat16(b);
    __nv_bfloat16 la = __float2bfloat16(a - __bfloat162float(ha));
    __nv_bfloat16 lb = __float2bfloat16(b - __bfloat162float(hb));
    __nv_bfloat162 vh(ha, hb), vl(la, lb);
    hi = *(uint32_t*)&vh;
    lo = *(uint32_t*)&vl;
}

// ---------------- split fp32 -> bf16 hi/lo (with scale) ----------------
__global__ __launch_bounds__(256)
void split_kernel(const float* __restrict__ src, __nv_bfloat16* __restrict__ hi,
                  __nv_bfloat16* __restrict__ lo, int n4, float scale)
{
    int i = blockIdx.x * blockDim.x + threadIdx.x;
    if (i >= n4) return;
    float4 v = ((const float4*)src)[i];
    v.x *= scale; v.y *= scale; v.z *= scale; v.w *= scale;
    uint32_t h0, l0, h1, l1;
    split_pack2(v.x, v.y, h0, l0);
    split_pack2(v.z, v.w, h1, l1);
    ((uint32_t*)hi)[2*i]   = h0;
    ((uint32_t*)hi)[2*i+1] = h1;
    ((uint32_t*)lo)[2*i]   = l0;
    ((uint32_t*)lo)[2*i+1] = l1;
}

// ---------------- cp.async double-buffered split-bf16 NT GEMM ----------------
// C 128x128 tile = Ah*Bh^T + Ah*Bl^T + Al*Bh^T. Output: fp32 (+bias) OR bf16 hi/lo (*cscale).
#define GBM 128
#define GBN 128
#define GBK 64
#define OP_BYTES (GBM * GBK * 2)      // 16384
#define OFF_AH 0
#define OFF_AL (OP_BYTES)
#define OFF_BH (2 * OP_BYTES)
#define OFF_BL (3 * OP_BYTES)
#define G_STAGE (4 * OP_BYTES)        // 65536
#define GEMM_SMEM (2 * G_STAGE)       // 131072

__device__ __forceinline__ void gemm_prefetch(
    uint32_t stage_base, const __nv_bfloat16* Ah, const __nv_bfloat16* Al,
    const __nv_bfloat16* Bh, const __nv_bfloat16* Bl,
    int row0, int col0, int Kdim, int koff, int tid)
{
    const int cc = tid & 7;
    #pragma unroll
    for (int i = 0; i < 4; ++i) {
        const int rr = (tid >> 3) + i * 32;
        const uint32_t so = (uint32_t)(rr * 128 + ((cc ^ (rr & 7)) << 4));
        const size_t ga = (size_t)(row0 + rr) * Kdim + koff + cc * 8;
        const size_t gb = (size_t)(col0 + rr) * Kdim + koff + cc * 8;
        CP_ASYNC16(stage_base + OFF_AH + so, Ah + ga);
        CP_ASYNC16(stage_base + OFF_AL + so, Al + ga);
        CP_ASYNC16(stage_base + OFF_BH + so, Bh + gb);
        CP_ASYNC16(stage_base + OFF_BL + so, Bl + gb);
    }
}

__global__ __launch_bounds__(256)
void gemm_mma_kernel(const __nv_bfloat16* __restrict__ Ah, const __nv_bfloat16* __restrict__ Al,
                     const __nv_bfloat16* __restrict__ Bh, const __nv_bfloat16* __restrict__ Bl,
                     float* __restrict__ C, const float* __restrict__ bias,
                     __nv_bfloat16* __restrict__ Ch, __nv_bfloat16* __restrict__ Cl,
                     float cscale, int Kdim, int ldc)
{
    extern __shared__ __align__(128) char smem[];
    const uint32_t sb = smem_u32(smem);

    const int tid  = threadIdx.x;
    const int warp = tid >> 5;
    const int lane = tid & 31;
    const int wm = warp & 1;
    const int wn = warp >> 1;
    const int row0 = blockIdx.y * GBM;
    const int col0 = blockIdx.x * GBN;

    float acc[4][4][4];
    #pragma unroll
    for (int a = 0; a < 4; ++a)
        #pragma unroll
        for (int b = 0; b < 4; ++b)
            #pragma unroll
            for (int c = 0; c < 4; ++c) acc[a][b][c] = 0.f;

    const int sub = lane >> 3;
    const int l7  = lane & 7;
    const int nchunk = Kdim / GBK;   // 16

    gemm_prefetch(sb, Ah, Al, Bh, Bl, row0, col0, Kdim, 0, tid);
    CP_COMMIT();

    for (int kc = 0; kc < nchunk; ++kc) {
        const int s = kc & 1;
        if (kc + 1 < nchunk) {
            gemm_prefetch(sb + (1 - s) * G_STAGE, Ah, Al, Bh, Bl, row0, col0, Kdim, (kc + 1) * GBK, tid);
            CP_COMMIT();
            CP_WAIT1();
        } else {
            CP_WAIT0();
        }
        __syncthreads();

        const uint32_t ss = sb + s * G_STAGE;
        #pragma unroll
        for (int ks = 0; ks < 4; ++ks) {
            uint32_t ah[4][4], al[4][4], bf[4][2];
            #pragma unroll
            for (int mt = 0; mt < 4; ++mt) {
                const int r  = wm * 64 + mt * 16 + ((sub & 1) << 3) + l7;
                const int ch = ks * 2 + (sub >> 1);
                const uint32_t ad = ss + (uint32_t)(r * 128 + ((ch ^ (r & 7)) << 4));
                LDSM_X4(ah[mt], ad + OFF_AH);
                LDSM_X4(al[mt], ad + OFF_AL);
            }
            #pragma unroll
            for (int np = 0; np < 2; ++np) {
                const int r  = wn * 32 + np * 16 + ((sub >> 1) << 3) + l7;
                const int ch = ks * 2 + (sub & 1);
                uint32_t t[4];
                LDSM_X4(t, ss + OFF_BH + (uint32_t)(r * 128 + ((ch ^ (r & 7)) << 4)));
                bf[np*2][0]   = t[0]; bf[np*2][1]   = t[1];
                bf[np*2+1][0] = t[2]; bf[np*2+1][1] = t[3];
            }
            #pragma unroll
            for (int mt = 0; mt < 4; ++mt)
                #pragma unroll
                for (int nt = 0; nt < 4; ++nt) {
                    MMA_BF16(acc[mt][nt], ah[mt], bf[nt][0], bf[nt][1]);
                    MMA_BF16(acc[mt][nt], al[mt], bf[nt][0], bf[nt][1]);
                }
            #pragma unroll
            for (int np = 0; np < 2; ++np) {
                const int r  = wn * 32 + np * 16 + ((sub >> 1) << 3) + l7;
                const int ch = ks * 2 + (sub & 1);
                uint32_t t[4];
                LDSM_X4(t, ss + OFF_BL + (uint32_t)(r * 128 + ((ch ^ (r & 7)) << 4)));
                bf[np*2][0]   = t[0]; bf[np*2][1]   = t[1];
                bf[np*2+1][0] = t[2]; bf[np*2+1][1] = t[3];
            }
            #pragma unroll
            for (int mt = 0; mt < 4; ++mt)
                #pragma unroll
                for (int nt = 0; nt < 4; ++nt)
                    MMA_BF16(acc[mt][nt], ah[mt], bf[nt][0], bf[nt][1]);
        }
        __syncthreads();
    }

    const int er = lane >> 2;
    const int ec = (lane & 3) * 2;
    if (Ch) {
        // fused split epilogue: write bf16 hi/lo of cscale*acc
        #pragma unroll
        for (int mt = 0; mt < 4; ++mt) {
            const int grow = row0 + wm * 64 + mt * 16 + er;
            #pragma unroll
            for (int nt = 0; nt < 4; ++nt) {
                const int gcol = col0 + wn * 32 + nt * 8 + ec;
                uint32_t h0, l0, h1, l1;
                split_pack2(acc[mt][nt][0] * cscale, acc[mt][nt][1] * cscale, h0, l0);
                split_pack2(acc[mt][nt][2] * cscale, acc[mt][nt][3] * cscale, h1, l1);
                *(uint32_t*)&Ch[(size_t)grow * ldc + gcol] = h0;
                *(uint32_t*)&Cl[(size_t)grow * ldc + gcol] = l0;
                *(uint32_t*)&Ch[(size_t)(grow + 8) * ldc + gcol] = h1;
                *(uint32_t*)&Cl[(size_t)(grow + 8) * ldc + gcol] = l1;
            }
        }
    } else {
        #pragma unroll
        for (int mt = 0; mt < 4; ++mt) {
            const int grow = row0 + wm * 64 + mt * 16 + er;
            #pragma unroll
            for (int nt = 0; nt < 4; ++nt) {
                const int gcol = col0 + wn * 32 + nt * 8 + ec;
                float bx = 0.f, by = 0.f;
                if (bias) { bx = bias[gcol]; by = bias[gcol + 1]; }
                *(float2*)&C[(size_t)grow * ldc + gcol] =
                    make_float2(acc[mt][nt][0] + bx, acc[mt][nt][1] + by);
                *(float2*)&C[(size_t)(grow + 8) * ldc + gcol] =
                    make_float2(acc[mt][nt][2] + bx, acc[mt][nt][3] + by);
            }
        }
    }
}

// ---------------- cp.async double-buffered HMMA flash attention ----------------
// Grid (T/128, NH, B), 256 thr. S = QhKh+QhKl+QlKh; PV = PhVh+PhVl+PlVh.
// Output written directly as bf16 hi/lo (fused split for the final GEMM).
#define FA_BN 64
#define FA_TILEB (FA_BN * 128)        // 8192
#define FA_STAGE (4 * FA_TILEB)       // 32768: Kh | Kl | Vh | Vl
#define FA_SMEM (2 * FA_STAGE)        // 65536

__device__ __forceinline__ void attn_prefetch(
    uint32_t stage_base, const __nv_bfloat16* Kh, const __nv_bfloat16* Kl,
    const __nv_bfloat16* Vh, const __nv_bfloat16* Vl,
    size_t rowbase, int colbase, int key0, int tid)
{
    #pragma unroll
    for (int i = 0; i < 2; ++i) {
        int u = tid + i * 256;
        int r = u >> 3, c = u & 7;
        const size_t g = (rowbase + key0 + r) * DM + colbase + c * 8;
        const uint32_t so = (uint32_t)(r * 128 + ((c ^ (r & 7)) << 4));
        CP_ASYNC16(stage_base + so,                Kh + g);
        CP_ASYNC16(stage_base + FA_TILEB + so,     Kl + g);
        CP_ASYNC16(stage_base + 2 * FA_TILEB + so, Vh + g);
        CP_ASYNC16(stage_base + 3 * FA_TILEB + so, Vl + g);
    }
}

__global__ __launch_bounds__(256)
void attn_mma_kernel(const __nv_bfloat16* __restrict__ Qh, const __nv_bfloat16* __restrict__ Ql,
                     const __nv_bfloat16* __restrict__ Kh, const __nv_bfloat16* __restrict__ Kl,
                     const __nv_bfloat16* __restrict__ Vh, const __nv_bfloat16* __restrict__ Vl,
                     __nv_bfloat16* __restrict__ Oh, __nv_bfloat16* __restrict__ Ol)
{
    extern __shared__ __align__(128) char sm[];
    const uint32_t sb = smem_u32(sm);

    const int tid  = threadIdx.x;
    const int warp = tid >> 5;
    const int lane = tid & 31;
    const int sub  = lane >> 3;
    const int l7   = lane & 7;
    const int h = blockIdx.y;
    const int b = blockIdx.z;
    const int q0 = blockIdx.x * 128;

    const size_t rowbase = (size_t)b * T_SZ;
    const int    colbase = h * HD;

    // ---- stage Q through buffer 0, keep hi/lo A fragments
    uint32_t qfh[4][4], qfl[4][4];
    #pragma unroll
    for (int pass = 0; pass < 2; ++pass) {
        const __nv_bfloat16* src = pass ? Ql : Qh;
        if (pass) __syncthreads();
        #pragma unroll
        for (int i = 0; i < 4; ++i) {
            int u = tid + i * 256;
            int r = u >> 3, c = u & 7;
            const uint4 v = *(const uint4*)(src + (rowbase + q0 + r) * DM + colbase + c * 8);
            *(uint4*)(sm + r * 128 + ((c ^ (r & 7)) << 4)) = v;
        }
        __syncthreads();
        #pragma unroll
        for (int t = 0; t < 4; ++t) {
            const int r  = warp * 16 + ((sub & 1) << 3) + l7;
            const int ch = t * 2 + (sub >> 1);
            const uint32_t ad = sb + (uint32_t)(r * 128 + ((ch ^ (r & 7)) << 4));
            if (pass) { LDSM_X4(qfl[t], ad); } else { LDSM_X4(qfh[t], ad); }
        }
    }
    __syncthreads();   // Q fragments extracted; buffer 0 free for cp.async

    float acc[8][4];
    #pragma unroll
    for (int j = 0; j < 8; ++j)
        #pragma unroll
        for (int c = 0; c < 4; ++c) acc[j][c] = 0.f;
    float m0 = -1e30f, m1 = -1e30f, l0 = 0.f, l1 = 0.f;

    attn_prefetch(sb, Kh, Kl, Vh, Vl, rowbase, colbase, 0, tid);
    CP_COMMIT();

    const int ntiles = T_SZ / FA_BN;   // 32
    for (int kt = 0; kt < ntiles; ++kt) {
        const int s = kt & 1;
        if (kt + 1 < ntiles) {
            attn_prefetch(sb + (1 - s) * FA_STAGE, Kh, Kl, Vh, Vl, rowbase, colbase, (kt + 1) * FA_BN, tid);
            CP_COMMIT();
            CP_WAIT1();
        } else {
            CP_WAIT0();
        }
        __syncthreads();
        const uint32_t ss = sb + s * FA_STAGE;

        // ---- S = Q K^T
        float st[8][4];
        #pragma unroll
        for (int j = 0; j < 8; ++j)
            #pragma unroll
            for (int c = 0; c < 4; ++c) st[j][c] = 0.f;

        #pragma unroll
        for (int np = 0; np < 4; ++np) {
            #pragma unroll
            for (int t = 0; t < 4; ++t) {
                const int r  = np * 16 + ((sub >> 1) << 3) + l7;
                const int ch = t * 2 + (sub & 1);
                const uint32_t so = (uint32_t)(r * 128 + ((ch ^ (r & 7)) << 4));
                uint32_t eh[4], el[4];
                LDSM_X4(eh, ss + so);
                LDSM_X4(el, ss + FA_TILEB + so);
                MMA_BF16(st[np*2],   qfh[t], eh[0], eh[1]);
                MMA_BF16(st[np*2+1], qfh[t], eh[2], eh[3]);
                MMA_BF16(st[np*2],   qfh[t], el[0], el[1]);
                MMA_BF16(st[np*2+1], qfh[t], el[2], el[3]);
                MMA_BF16(st[np*2],   qfl[t], eh[0], eh[1]);
                MMA_BF16(st[np*2+1], qfl[t], eh[2], eh[3]);
            }
        }

        // ---- online softmax (log2 domain; Q pre-scaled by 0.125*log2e)
        float tm0 = st[0][0], tm1 = st[0][2];
        #pragma unroll
        for (int j = 0; j < 8; ++j) {
            tm0 = fmaxf(tm0, fmaxf(st[j][0], st[j][1]));
            tm1 = fmaxf(tm1, fmaxf(st[j][2], st[j][3]));
        }
        tm0 = fmaxf(tm0, __shfl_xor_sync(0xffffffffu, tm0, 1));
        tm0 = fmaxf(tm0, __shfl_xor_sync(0xffffffffu, tm0, 2));
        tm1 = fmaxf(tm1, __shfl_xor_sync(0xffffffffu, tm1, 1));
        tm1 = fmaxf(tm1, __shfl_xor_sync(0xffffffffu, tm1, 2));
        const float nm0 = fmaxf(m0, tm0), nm1 = fmaxf(m1, tm1);
        const float c0 = exp2f(m0 - nm0), c1 = exp2f(m1 - nm1);
        m0 = nm0; m1 = nm1;
        l0 *= c0; l1 *= c1;
        #pragma unroll
        for (int j = 0; j < 8; ++j) {
            acc[j][0] *= c0; acc[j][1] *= c0;
            acc[j][2] *= c1; acc[j][3] *= c1;
        }
        #pragma unroll
        for (int j = 0; j < 8; ++j) {
            st[j][0] = exp2f(st[j][0] - m0);
            st[j][1] = exp2f(st[j][1] - m0);
            st[j][2] = exp2f(st[j][2] - m1);
            st[j][3] = exp2f(st[j][3] - m1);
            l0 += st[j][0] + st[j][1];
            l1 += st[j][2] + st[j][3];
        }

        // ---- split-pack P into hi/lo fragments
        uint32_t pfh[4][4], pfl[4][4];
        #pragma unroll
        for (int t = 0; t < 4; ++t) {
            split_pack2(st[2*t][0],   st[2*t][1],   pfh[t][0], pfl[t][0]);
            split_pack2(st[2*t][2],   st[2*t][3],   pfh[t][1], pfl[t][1]);
            split_pack2(st[2*t+1][0], st[2*t+1][1], pfh[t][2], pfl[t][2]);
            split_pack2(st[2*t+1][2], st[2*t+1][3], pfh[t][3], pfl[t][3]);
        }

        // ---- acc += P V
        #pragma unroll
        for (int t = 0; t < 4; ++t) {
            #pragma unroll
            for (int dp = 0; dp < 4; ++dp) {
                const int r  = t * 16 + ((sub & 1) << 3) + l7;
                const int ch = dp * 2 + (sub >> 1);
                const uint32_t so = (uint32_t)(r * 128 + ((ch ^ (r & 7)) << 4));
                uint32_t vh[4], vl[4];
                LDSM_X4_T(vh, ss + 2 * FA_TILEB + so);
                LDSM_X4_T(vl, ss + 3 * FA_TILEB + so);
                MMA_BF16(acc[dp*2],   pfh[t], vh[0], vh[1]);
                MMA_BF16(acc[dp*2+1], pfh[t], vh[2], vh[3]);
                MMA_BF16(acc[dp*2],   pfh[t], vl[0], vl[1]);
                MMA_BF16(acc[dp*2+1], pfh[t], vl[2], vl[3]);
                MMA_BF16(acc[dp*2],   pfl[t], vh[0], vh[1]);
                MMA_BF16(acc[dp*2+1], pfl[t], vh[2], vh[3]);
            }
        }
        __syncthreads();
    }

    // ---- finalize + fused bf16 split of output
    l0 += __shfl_xor_sync(0xffffffffu, l0, 1);
    l0 += __shfl_xor_sync(0xffffffffu, l0, 2);
    l1 += __shfl_xor_sync(0xffffffffu, l1, 1);
    l1 += __shfl_xor_sync(0xffffffffu, l1, 2);
    const float inv0 = 1.f / (l0 + 1e-8f);
    const float inv1 = 1.f / (l1 + 1e-8f);

    const int r0 = q0 + warp * 16 + (lane >> 2);
    const int ec = (lane & 3) * 2;
    #pragma unroll
    for (int j = 0; j < 8; ++j) {
        const int gcol = colbase + j * 8 + ec;
        uint32_t h0, lo0, h1, lo1;
        split_pack2(acc[j][0] * inv0, acc[j][1] * inv0, h0, lo0);
        split_pack2(acc[j][2] * inv1, acc[j][3] * inv1, h1, lo1);
        *(uint32_t*)&Oh[(rowbase + r0) * DM + gcol] = h0;
        *(uint32_t*)&Ol[(rowbase + r0) * DM + gcol] = lo0;
        *(uint32_t*)&Oh[(rowbase + r0 + 8) * DM + gcol] = h1;
        *(uint32_t*)&Ol[(rowbase + r0 + 8) * DM + gcol] = lo1;
    }
}

// ---------------- launch ----------------
extern "C" void kernel_launch(void* const* d_in, const int* in_sizes, int n_in,
                              void* d_out, int out_size)
{
    const float* x  = (const float*)d_in[0];
    const float* Wq = (const float*)d_in[1];
    const float* Wk = (const float*)d_in[2];
    const float* Wv = (const float*)d_in[3];
    const float* Wo = (const float*)d_in[4];
    const float* bo = (const float*)d_in[5];
    float* out = (float*)d_out;

    __nv_bfloat16 *xh, *xl, *oh, *ol, *qh, *ql, *kh, *kl, *vh, *vl;
    __nv_bfloat16 *wqh, *wql, *wkh, *wkl, *wvh, *wvl, *woh, *wol;
    cudaGetSymbolAddress((void**)&xh, g_xh);
    cudaGetSymbolAddress((void**)&xl, g_xl);
    cudaGetSymbolAddress((void**)&oh, g_oh);
    cudaGetSymbolAddress((void**)&ol, g_ol);
    cudaGetSymbolAddress((void**)&qh, g_qh);
    cudaGetSymbolAddress((void**)&ql, g_ql);
    cudaGetSymbolAddress((void**)&kh, g_kh);
    cudaGetSymbolAddress((void**)&kl, g_kl);
    cudaGetSymbolAddress((void**)&vh, g_vh);
    cudaGetSymbolAddress((void**)&vl, g_vl);
    cudaGetSymbolAddress((void**)&wqh, g_wqh);
    cudaGetSymbolAddress((void**)&wql, g_wql);
    cudaGetSymbolAddress((void**)&wkh, g_wkh);
    cudaGetSymbolAddress((void**)&wkl, g_wkl);
    cudaGetSymbolAddress((void**)&wvh, g_wvh);
    cudaGetSymbolAddress((void**)&wvl, g_wvl);
    cudaGetSymbolAddress((void**)&woh, g_woh);
    cudaGetSymbolAddress((void**)&wol, g_wol);

    cudaFuncSetAttribute(gemm_mma_kernel, cudaFuncAttributeMaxDynamicSharedMemorySize, GEMM_SMEM);
    cudaFuncSetAttribute(attn_mma_kernel, cudaFuncAttributeMaxDynamicSharedMemorySize, FA_SMEM);

    const int n4x = NELEM / 4;
    const int n4w = (DM * DM) / 4;
    split_kernel<<<n4x / 256, 256>>>(x, xh, xl, n4x, 1.0f);
    split_kernel<<<n4w / 256, 256>>>(Wq, wqh, wql, n4w, 1.0f);
    split_kernel<<<n4w / 256, 256>>>(Wk, wkh, wkl, n4w, 1.0f);
    split_kernel<<<n4w / 256, 256>>>(Wv, wvh, wvl, n4w, 1.0f);
    split_kernel<<<n4w / 256, 256>>>(Wo, woh, wol, n4w, 1.0f);

    // Q/K/V projections: fused split epilogue (Q pre-scaled into log2-softmax domain)
    const float qscale = 0.125f * 1.44269504088896341f;   // (1/sqrt(64)) * log2(e)
    dim3 ggrid(DM / GBN, MROWS / GBM);   // (8, 64)
    gemm_mma_kernel<<<ggrid, 256, GEMM_SMEM>>>(xh, xl, wqh, wql, nullptr, nullptr, qh, ql, qscale, DM, DM);
    gemm_mma_kernel<<<ggrid, 256, GEMM_SMEM>>>(xh, xl, wkh, wkl, nullptr, nullptr, kh, kl, 1.0f, DM, DM);
    gemm_mma_kernel<<<ggrid, 256, GEMM_SMEM>>>(xh, xl, wvh, wvl, nullptr, nullptr, vh, vl, 1.0f, DM, DM);

    // attention: writes oh/ol directly
    dim3 agrid(T_SZ / 128, NH, B_SZ);    // (16, 16, 4)
    attn_mma_kernel<<<agrid, 256, FA_SMEM>>>(qh, ql, kh, kl, vh, vl, oh, ol);

    // output projection (+bias), fp32 out
    gemm_mma_kernel<<<ggrid, 256, GEMM_SMEM>>>(oh, ol, woh, wol, out, bo, nullptr, nullptr, 1.0f, DM, DM);
}

// round 14
// speedup vs baseline: 3.9212x; 1.0510x over previous
#include <cuda_runtime.h>
#include <cuda_bf16.h>
#include <cstdint>
#include <math.h>

// Problem constants
#define B_SZ 4
#define T_SZ 2048
#define DM   1024
#define NH   16
#define HD   64
#define MROWS (B_SZ * T_SZ)   // 8192
#define NELEM (MROWS * DM)

// ---------------- scratch (allocation-free) ----------------
__device__ __nv_bfloat16 g_xh[NELEM];
__device__ __nv_bfloat16 g_xl[NELEM];
__device__ __nv_bfloat16 g_oh[NELEM];
__device__ __nv_bfloat16 g_ol[NELEM];
__device__ __nv_bfloat16 g_qh[NELEM];
__device__ __nv_bfloat16 g_ql[NELEM];
__device__ __nv_bfloat16 g_kh[NELEM];
__device__ __nv_bfloat16 g_kl[NELEM];
__device__ __nv_bfloat16 g_vh[NELEM];
__device__ __nv_bfloat16 g_vl[NELEM];
__device__ __nv_bfloat16 g_wqh[DM * DM];
__device__ __nv_bfloat16 g_wql[DM * DM];
__device__ __nv_bfloat16 g_wkh[DM * DM];
__device__ __nv_bfloat16 g_wkl[DM * DM];
__device__ __nv_bfloat16 g_wvh[DM * DM];
__device__ __nv_bfloat16 g_wvl[DM * DM];
__device__ __nv_bfloat16 g_woh[DM * DM];
__device__ __nv_bfloat16 g_wol[DM * DM];

// ---------------- helpers ----------------
__device__ __forceinline__ uint32_t smem_u32(const void* p) {
    uint32_t a;
    asm("{ .reg .u64 t; cvta.to.shared.u64 t, %1; cvt.u32.u64 %0, t; }" : "=r"(a) : "l"(p));
    return a;
}

#define LDSM_X4(r, addr) \
    asm volatile("ldmatrix.sync.aligned.m8n8.x4.shared.b16 {%0,%1,%2,%3}, [%4];" \
        : "=r"((r)[0]), "=r"((r)[1]), "=r"((r)[2]), "=r"((r)[3]) : "r"(addr))

#define LDSM_X4_T(r, addr) \
    asm volatile("ldmatrix.sync.aligned.m8n8.x4.trans.shared.b16 {%0,%1,%2,%3}, [%4];" \
        : "=r"((r)[0]), "=r"((r)[1]), "=r"((r)[2]), "=r"((r)[3]) : "r"(addr))

#define MMA_BF16(d, a, b0, b1) \
    asm volatile("mma.sync.aligned.m16n8k16.row.col.f32.bf16.bf16.f32 " \
        "{%0,%1,%2,%3}, {%4,%5,%6,%7}, {%8,%9}, {%0,%1,%2,%3};" \
        : "+f"((d)[0]), "+f"((d)[1]), "+f"((d)[2]), "+f"((d)[3]) \
        : "r"((a)[0]), "r"((a)[1]), "r"((a)[2]), "r"((a)[3]), "r"(b0), "r"(b1))

#define CP_ASYNC16(saddr, gptr) \
    asm volatile("cp.async.cg.shared.global [%0], [%1], 16;" :: "r"(saddr), "l"(gptr))
#define CP_COMMIT() asm volatile("cp.async.commit_group;" ::: "memory")
#define CP_WAIT0()  asm volatile("cp.async.wait_group 0;" ::: "memory")
#define CP_WAIT1()  asm volatile("cp.async.wait_group 1;" ::: "memory")

// split-pack two fp32 into bf16x2 hi + bf16x2 lo
__device__ __forceinline__ void split_pack2(float a, float b, uint32_t& hi, uint32_t& lo) {
    __nv_bfloat16 ha = __float2bfloat16(a);
    __nv_bfloat16 hb = __float2bfloat16(b);
    __nv_bfloat16 la = __float2bfloat16(a - __bfloat162float(ha));
    __nv_bfloat16 lb = __float2bfloat16(b - __bfloat162float(hb));
    __nv_bfloat162 vh(ha, hb), vl(la, lb);
    hi = *(uint32_t*)&vh;
    lo = *(uint32_t*)&vl;
}

// ---------------- split fp32 -> bf16 hi/lo (with scale) ----------------
__global__ __launch_bounds__(256)
void split_kernel(const float* __restrict__ src, __nv_bfloat16* __restrict__ hi,
                  __nv_bfloat16* __restrict__ lo, int n4, float scale)
{
    int i = blockIdx.x * blockDim.x + threadIdx.x;
    if (i >= n4) return;
    float4 v = ((const float4*)src)[i];
    v.x *= scale; v.y *= scale; v.z *= scale; v.w *= scale;
    uint32_t h0, l0, h1, l1;
    split_pack2(v.x, v.y, h0, l0);
    split_pack2(v.z, v.w, h1, l1);
    ((uint32_t*)hi)[2*i]   = h0;
    ((uint32_t*)hi)[2*i+1] = h1;
    ((uint32_t*)lo)[2*i]   = l0;
    ((uint32_t*)lo)[2*i+1] = l1;
}

// ---------------- cp.async double-buffered split-bf16 NT GEMM (GBK=32, 2 CTAs/SM) ----------------
// 64B rows in smem; swizzle: chunk c (0..3) -> c ^ ((r>>1)&3).
#define GBM 128
#define GBN 128
#define GBK 32
#define OP_BYTES (GBM * GBK * 2)      // 8192
#define OFF_AH 0
#define OFF_AL (OP_BYTES)
#define OFF_BH (2 * OP_BYTES)
#define OFF_BL (3 * OP_BYTES)
#define G_STAGE (4 * OP_BYTES)        // 32768
#define GEMM_SMEM (2 * G_STAGE)       // 65536

__device__ __forceinline__ uint32_t gsw(int r, int c) {   // 64B-row swizzled byte offset
    return (uint32_t)(r * 64 + ((c ^ ((r >> 1) & 3)) << 4));
}

__device__ __forceinline__ void gemm_prefetch(
    uint32_t stage_base, const __nv_bfloat16* Ah, const __nv_bfloat16* Al,
    const __nv_bfloat16* Bh, const __nv_bfloat16* Bl,
    int row0, int col0, int Kdim, int koff, int tid)
{
    const int cc = tid & 3;          // chunk 0..3
    const int rr0 = tid >> 2;        // 0..63
    #pragma unroll
    for (int i = 0; i < 2; ++i) {
        const int rr = rr0 + i * 64;
        const uint32_t so = gsw(rr, cc);
        const size_t ga = (size_t)(row0 + rr) * Kdim + koff + cc * 8;
        const size_t gb = (size_t)(col0 + rr) * Kdim + koff + cc * 8;
        CP_ASYNC16(stage_base + OFF_AH + so, Ah + ga);
        CP_ASYNC16(stage_base + OFF_AL + so, Al + ga);
        CP_ASYNC16(stage_base + OFF_BH + so, Bh + gb);
        CP_ASYNC16(stage_base + OFF_BL + so, Bl + gb);
    }
}

// Shared GEMM body. If Ch != nullptr: write bf16 hi/lo of cscale*acc; else fp32 C (+bias).
__device__ __forceinline__ void gemm_body(
    const __nv_bfloat16* __restrict__ Ah, const __nv_bfloat16* __restrict__ Al,
    const __nv_bfloat16* __restrict__ Bh, const __nv_bfloat16* __restrict__ Bl,
    float* __restrict__ C, const float* __restrict__ bias,
    __nv_bfloat16* __restrict__ Ch, __nv_bfloat16* __restrict__ Cl,
    float cscale, int Kdim, int ldc, char* smem)
{
    const uint32_t sb = smem_u32(smem);
    const int tid  = threadIdx.x;
    const int warp = tid >> 5;
    const int lane = tid & 31;
    const int wm = warp & 1;
    const int wn = warp >> 1;
    const int row0 = blockIdx.y * GBM;
    const int col0 = blockIdx.x * GBN;

    float acc[4][4][4];
    #pragma unroll
    for (int a = 0; a < 4; ++a)
        #pragma unroll
        for (int b = 0; b < 4; ++b)
            #pragma unroll
            for (int c = 0; c < 4; ++c) acc[a][b][c] = 0.f;

    const int sub = lane >> 3;
    const int l7  = lane & 7;
    const int nchunk = Kdim / GBK;   // 32

    gemm_prefetch(sb, Ah, Al, Bh, Bl, row0, col0, Kdim, 0, tid);
    CP_COMMIT();

    for (int kc = 0; kc < nchunk; ++kc) {
        const int s = kc & 1;
        if (kc + 1 < nchunk) {
            gemm_prefetch(sb + (1 - s) * G_STAGE, Ah, Al, Bh, Bl, row0, col0, Kdim, (kc + 1) * GBK, tid);
            CP_COMMIT();
            CP_WAIT1();
        } else {
            CP_WAIT0();
        }
        __syncthreads();

        const uint32_t ss = sb + s * G_STAGE;
        #pragma unroll
        for (int ks = 0; ks < 2; ++ks) {
            uint32_t ah[4][4], al[4][4], bf[4][2];
            #pragma unroll
            for (int mt = 0; mt < 4; ++mt) {
                const int r  = wm * 64 + mt * 16 + ((sub & 1) << 3) + l7;
                const int ch = ks * 2 + (sub >> 1);
                const uint32_t ad = ss + gsw(r, ch);
                LDSM_X4(ah[mt], ad + OFF_AH);
                LDSM_X4(al[mt], ad + OFF_AL);
            }
            #pragma unroll
            for (int np = 0; np < 2; ++np) {
                const int r  = wn * 32 + np * 16 + ((sub >> 1) << 3) + l7;
                const int ch = ks * 2 + (sub & 1);
                uint32_t t[4];
                LDSM_X4(t, ss + OFF_BH + gsw(r, ch));
                bf[np*2][0]   = t[0]; bf[np*2][1]   = t[1];
                bf[np*2+1][0] = t[2]; bf[np*2+1][1] = t[3];
            }
            #pragma unroll
            for (int mt = 0; mt < 4; ++mt)
                #pragma unroll
                for (int nt = 0; nt < 4; ++nt) {
                    MMA_BF16(acc[mt][nt], ah[mt], bf[nt][0], bf[nt][1]);
                    MMA_BF16(acc[mt][nt], al[mt], bf[nt][0], bf[nt][1]);
                }
            #pragma unroll
            for (int np = 0; np < 2; ++np) {
                const int r  = wn * 32 + np * 16 + ((sub >> 1) << 3) + l7;
                const int ch = ks * 2 + (sub & 1);
                uint32_t t[4];
                LDSM_X4(t, ss + OFF_BL + gsw(r, ch));
                bf[np*2][0]   = t[0]; bf[np*2][1]   = t[1];
                bf[np*2+1][0] = t[2]; bf[np*2+1][1] = t[3];
            }
            #pragma unroll
            for (int mt = 0; mt < 4; ++mt)
                #pragma unroll
                for (int nt = 0; nt < 4; ++nt)
                    MMA_BF16(acc[mt][nt], ah[mt], bf[nt][0], bf[nt][1]);
        }
        __syncthreads();
    }

    const int er = lane >> 2;
    const int ec = (lane & 3) * 2;
    if (Ch) {
        #pragma unroll
        for (int mt = 0; mt < 4; ++mt) {
            const int grow = row0 + wm * 64 + mt * 16 + er;
            #pragma unroll
            for (int nt = 0; nt < 4; ++nt) {
                const int gcol = col0 + wn * 32 + nt * 8 + ec;
                uint32_t h0, l0, h1, l1;
                split_pack2(acc[mt][nt][0] * cscale, acc[mt][nt][1] * cscale, h0, l0);
                split_pack2(acc[mt][nt][2] * cscale, acc[mt][nt][3] * cscale, h1, l1);
                *(uint32_t*)&Ch[(size_t)grow * ldc + gcol] = h0;
                *(uint32_t*)&Cl[(size_t)grow * ldc + gcol] = l0;
                *(uint32_t*)&Ch[(size_t)(grow + 8) * ldc + gcol] = h1;
                *(uint32_t*)&Cl[(size_t)(grow + 8) * ldc + gcol] = l1;
            }
        }
    } else {
        #pragma unroll
        for (int mt = 0; mt < 4; ++mt) {
            const int grow = row0 + wm * 64 + mt * 16 + er;
            #pragma unroll
            for (int nt = 0; nt < 4; ++nt) {
                const int gcol = col0 + wn * 32 + nt * 8 + ec;
                float bx = 0.f, by = 0.f;
                if (bias) { bx = bias[gcol]; by = bias[gcol + 1]; }
                *(float2*)&C[(size_t)grow * ldc + gcol] =
                    make_float2(acc[mt][nt][0] + bx, acc[mt][nt][1] + by);
                *(float2*)&C[(size_t)(grow + 8) * ldc + gcol] =
                    make_float2(acc[mt][nt][2] + bx, acc[mt][nt][3] + by);
            }
        }
    }
}

// Fused Q/K/V projection: grid.z = 0/1/2 selects weights + outputs.
__global__ __launch_bounds__(256, 2)
void gemm_qkv_kernel(const __nv_bfloat16* __restrict__ xh, const __nv_bfloat16* __restrict__ xl,
                     float qscale)
{
    extern __shared__ __align__(128) char smem[];
    const int z = blockIdx.z;
    const __nv_bfloat16* Bh = (z == 0) ? g_wqh : (z == 1) ? g_wkh : g_wvh;
    const __nv_bfloat16* Bl = (z == 0) ? g_wql : (z == 1) ? g_wkl : g_wvl;
    __nv_bfloat16* Ch = (z == 0) ? g_qh : (z == 1) ? g_kh : g_vh;
    __nv_bfloat16* Cl = (z == 0) ? g_ql : (z == 1) ? g_kl : g_vl;
    const float cs = (z == 0) ? qscale : 1.0f;
    gemm_body(xh, xl, Bh, Bl, nullptr, nullptr, Ch, Cl, cs, DM, DM, smem);
}

// Output projection: fp32 out + bias.
__global__ __launch_bounds__(256, 2)
void gemm_out_kernel(const __nv_bfloat16* __restrict__ Ah, const __nv_bfloat16* __restrict__ Al,
                     float* __restrict__ C, const float* __restrict__ bias)
{
    extern __shared__ __align__(128) char smem[];
    gemm_body(Ah, Al, g_woh, g_wol, C, bias, nullptr, nullptr, 1.0f, DM, DM, smem);
}

// ---------------- cp.async double-buffered HMMA flash attention ----------------
#define FA_BN 64
#define FA_TILEB (FA_BN * 128)        // 8192 (128B rows: 64 bf16)
#define FA_STAGE (4 * FA_TILEB)       // 32768: Kh | Kl | Vh | Vl
#define FA_SMEM (2 * FA_STAGE)        // 65536

__device__ __forceinline__ void attn_prefetch(
    uint32_t stage_base, const __nv_bfloat16* Kh, const __nv_bfloat16* Kl,
    const __nv_bfloat16* Vh, const __nv_bfloat16* Vl,
    size_t rowbase, int colbase, int key0, int tid)
{
    #pragma unroll
    for (int i = 0; i < 2; ++i) {
        int u = tid + i * 256;
        int r = u >> 3, c = u & 7;
        const size_t g = (rowbase + key0 + r) * DM + colbase + c * 8;
        const uint32_t so = (uint32_t)(r * 128 + ((c ^ (r & 7)) << 4));
        CP_ASYNC16(stage_base + so,                Kh + g);
        CP_ASYNC16(stage_base + FA_TILEB + so,     Kl + g);
        CP_ASYNC16(stage_base + 2 * FA_TILEB + so, Vh + g);
        CP_ASYNC16(stage_base + 3 * FA_TILEB + so, Vl + g);
    }
}

__global__ __launch_bounds__(256)
void attn_mma_kernel(const __nv_bfloat16* __restrict__ Qh, const __nv_bfloat16* __restrict__ Ql,
                     const __nv_bfloat16* __restrict__ Kh, const __nv_bfloat16* __restrict__ Kl,
                     const __nv_bfloat16* __restrict__ Vh, const __nv_bfloat16* __restrict__ Vl,
                     __nv_bfloat16* __restrict__ Oh, __nv_bfloat16* __restrict__ Ol)
{
    extern __shared__ __align__(128) char sm[];
    const uint32_t sb = smem_u32(sm);

    const int tid  = threadIdx.x;
    const int warp = tid >> 5;
    const int lane = tid & 31;
    const int sub  = lane >> 3;
    const int l7   = lane & 7;
    const int h = blockIdx.y;
    const int b = blockIdx.z;
    const int q0 = blockIdx.x * 128;

    const size_t rowbase = (size_t)b * T_SZ;
    const int    colbase = h * HD;

    // stage Q through buffer 0, keep hi/lo A fragments
    uint32_t qfh[4][4], qfl[4][4];
    #pragma unroll
    for (int pass = 0; pass < 2; ++pass) {
        const __nv_bfloat16* src = pass ? Ql : Qh;
        if (pass) __syncthreads();
        #pragma unroll
        for (int i = 0; i < 4; ++i) {
            int u = tid + i * 256;
            int r = u >> 3, c = u & 7;
            const uint4 v = *(const uint4*)(src + (rowbase + q0 + r) * DM + colbase + c * 8);
            *(uint4*)(sm + r * 128 + ((c ^ (r & 7)) << 4)) = v;
        }
        __syncthreads();
        #pragma unroll
        for (int t = 0; t < 4; ++t) {
            const int r  = warp * 16 + ((sub & 1) << 3) + l7;
            const int ch = t * 2 + (sub >> 1);
            const uint32_t ad = sb + (uint32_t)(r * 128 + ((ch ^ (r & 7)) << 4));
            if (pass) { LDSM_X4(qfl[t], ad); } else { LDSM_X4(qfh[t], ad); }
        }
    }
    __syncthreads();

    float acc[8][4];
    #pragma unroll
    for (int j = 0; j < 8; ++j)
        #pragma unroll
        for (int c = 0; c < 4; ++c) acc[j][c] = 0.f;
    float m0 = -1e30f, m1 = -1e30f, l0 = 0.f, l1 = 0.f;

    attn_prefetch(sb, Kh, Kl, Vh, Vl, rowbase, colbase, 0, tid);
    CP_COMMIT();

    const int ntiles = T_SZ / FA_BN;   // 32
    for (int kt = 0; kt < ntiles; ++kt) {
        const int s = kt & 1;
        if (kt + 1 < ntiles) {
            attn_prefetch(sb + (1 - s) * FA_STAGE, Kh, Kl, Vh, Vl, rowbase, colbase, (kt + 1) * FA_BN, tid);
            CP_COMMIT();
            CP_WAIT1();
        } else {
            CP_WAIT0();
        }
        __syncthreads();
        const uint32_t ss = sb + s * FA_STAGE;

        // S = Q K^T (QhKh + QhKl + QlKh)
        float st[8][4];
        #pragma unroll
        for (int j = 0; j < 8; ++j)
            #pragma unroll
            for (int c = 0; c < 4; ++c) st[j][c] = 0.f;

        #pragma unroll
        for (int np = 0; np < 4; ++np) {
            #pragma unroll
            for (int t = 0; t < 4; ++t) {
                const int r  = np * 16 + ((sub >> 1) << 3) + l7;
                const int ch = t * 2 + (sub & 1);
                const uint32_t so = (uint32_t)(r * 128 + ((ch ^ (r & 7)) << 4));
                uint32_t eh[4], el[4];
                LDSM_X4(eh, ss + so);
                LDSM_X4(el, ss + FA_TILEB + so);
                MMA_BF16(st[np*2],   qfh[t], eh[0], eh[1]);
                MMA_BF16(st[np*2+1], qfh[t], eh[2], eh[3]);
                MMA_BF16(st[np*2],   qfh[t], el[0], el[1]);
                MMA_BF16(st[np*2+1], qfh[t], el[2], el[3]);
                MMA_BF16(st[np*2],   qfl[t], eh[0], eh[1]);
                MMA_BF16(st[np*2+1], qfl[t], eh[2], eh[3]);
            }
        }

        // online softmax (log2 domain)
        float tm0 = st[0][0], tm1 = st[0][2];
        #pragma unroll
        for (int j = 0; j < 8; ++j) {
            tm0 = fmaxf(tm0, fmaxf(st[j][0], st[j][1]));
            tm1 = fmaxf(tm1, fmaxf(st[j][2], st[j][3]));
        }
        tm0 = fmaxf(tm0, __shfl_xor_sync(0xffffffffu, tm0, 1));
        tm0 = fmaxf(tm0, __shfl_xor_sync(0xffffffffu, tm0, 2));
        tm1 = fmaxf(tm1, __shfl_xor_sync(0xffffffffu, tm1, 1));
        tm1 = fmaxf(tm1, __shfl_xor_sync(0xffffffffu, tm1, 2));
        const float nm0 = fmaxf(m0, tm0), nm1 = fmaxf(m1, tm1);
        const float c0 = exp2f(m0 - nm0), c1 = exp2f(m1 - nm1);
        m0 = nm0; m1 = nm1;
        // rescale only when some lane's max actually moved (c != 1)
        if (__any_sync(0xffffffffu, (c0 != 1.f) | (c1 != 1.f))) {
            l0 *= c0; l1 *= c1;
            #pragma unroll
            for (int j = 0; j < 8; ++j) {
                acc[j][0] *= c0; acc[j][1] *= c0;
                acc[j][2] *= c1; acc[j][3] *= c1;
            }
        }
        #pragma unroll
        for (int j = 0; j < 8; ++j) {
            st[j][0] = exp2f(st[j][0] - m0);
            st[j][1] = exp2f(st[j][1] - m0);
            st[j][2] = exp2f(st[j][2] - m1);
            st[j][3] = exp2f(st[j][3] - m1);
            l0 += st[j][0] + st[j][1];
            l1 += st[j][2] + st[j][3];
        }

        // split-pack P into hi/lo fragments
        uint32_t pfh[4][4], pfl[4][4];
        #pragma unroll
        for (int t = 0; t < 4; ++t) {
            split_pack2(st[2*t][0],   st[2*t][1],   pfh[t][0], pfl[t][0]);
            split_pack2(st[2*t][2],   st[2*t][3],   pfh[t][1], pfl[t][1]);
            split_pack2(st[2*t+1][0], st[2*t+1][1], pfh[t][2], pfl[t][2]);
            split_pack2(st[2*t+1][2], st[2*t+1][3], pfh[t][3], pfl[t][3]);
        }

        // acc += P V  (PhVh + PhVl + PlVh)
        #pragma unroll
        for (int t = 0; t < 4; ++t) {
            #pragma unroll
            for (int dp = 0; dp < 4; ++dp) {
                const int r  = t * 16 + ((sub & 1) << 3) + l7;
                const int ch = dp * 2 + (sub >> 1);
                const uint32_t so = (uint32_t)(r * 128 + ((ch ^ (r & 7)) << 4));
                uint32_t vh[4], vl[4];
                LDSM_X4_T(vh, ss + 2 * FA_TILEB + so);
                LDSM_X4_T(vl, ss + 3 * FA_TILEB + so);
                MMA_BF16(acc[dp*2],   pfh[t], vh[0], vh[1]);
                MMA_BF16(acc[dp*2+1], pfh[t], vh[2], vh[3]);
                MMA_BF16(acc[dp*2],   pfh[t], vl[0], vl[1]);
                MMA_BF16(acc[dp*2+1], pfh[t], vl[2], vl[3]);
                MMA_BF16(acc[dp*2],   pfl[t], vh[0], vh[1]);
                MMA_BF16(acc[dp*2+1], pfl[t], vh[2], vh[3]);
            }
        }
        __syncthreads();
    }

    // finalize + fused bf16 split of output
    l0 += __shfl_xor_sync(0xffffffffu, l0, 1);
    l0 += __shfl_xor_sync(0xffffffffu, l0, 2);
    l1 += __shfl_xor_sync(0xffffffffu, l1, 1);
    l1 += __shfl_xor_sync(0xffffffffu, l1, 2);
    const float inv0 = 1.f / (l0 + 1e-8f);
    const float inv1 = 1.f / (l1 + 1e-8f);

    const int r0 = q0 + warp * 16 + (lane >> 2);
    const int ec = (lane & 3) * 2;
    #pragma unroll
    for (int j = 0; j < 8; ++j) {
        const int gcol = colbase + j * 8 + ec;
        uint32_t h0, lo0, h1, lo1;
        split_pack2(acc[j][0] * inv0, acc[j][1] * inv0, h0, lo0);
        split_pack2(acc[j][2] * inv1, acc[j][3] * inv1, h1, lo1);
        *(uint32_t*)&Oh[(rowbase + r0) * DM + gcol] = h0;
        *(uint32_t*)&Ol[(rowbase + r0) * DM + gcol] = lo0;
        *(uint32_t*)&Oh[(rowbase + r0 + 8) * DM + gcol] = h1;
        *(uint32_t*)&Ol[(rowbase + r0 + 8) * DM + gcol] = lo1;
    }
}

// ---------------- launch ----------------
extern "C" void kernel_launch(void* const* d_in, const int* in_sizes, int n_in,
                              void* d_out, int out_size)
{
    const float* x  = (const float*)d_in[0];
    const float* Wq = (const float*)d_in[1];
    const float* Wk = (const float*)d_in[2];
    const float* Wv = (const float*)d_in[3];
    const float* Wo = (const float*)d_in[4];
    const float* bo = (const float*)d_in[5];
    float* out = (float*)d_out;

    __nv_bfloat16 *xh, *xl, *oh, *ol, *qh, *ql, *kh, *kl, *vh, *vl;
    __nv_bfloat16 *wqh, *wql, *wkh, *wkl, *wvh, *wvl, *woh, *wol;
    cudaGetSymbolAddress((void**)&xh, g_xh);
    cudaGetSymbolAddress((void**)&xl, g_xl);
    cudaGetSymbolAddress((void**)&oh, g_oh);
    cudaGetSymbolAddress((void**)&ol, g_ol);
    cudaGetSymbolAddress((void**)&qh, g_qh);
    cudaGetSymbolAddress((void**)&ql, g_ql);
    cudaGetSymbolAddress((void**)&kh, g_kh);
    cudaGetSymbolAddress((void**)&kl, g_kl);
    cudaGetSymbolAddress((void**)&vh, g_vh);
    cudaGetSymbolAddress((void**)&vl, g_vl);
    cudaGetSymbolAddress((void**)&wqh, g_wqh);
    cudaGetSymbolAddress((void**)&wql, g_wql);
    cudaGetSymbolAddress((void**)&wkh, g_wkh);
    cudaGetSymbolAddress((void**)&wkl, g_wkl);
    cudaGetSymbolAddress((void**)&wvh, g_wvh);
    cudaGetSymbolAddress((void**)&wvl, g_wvl);
    cudaGetSymbolAddress((void**)&woh, g_woh);
    cudaGetSymbolAddress((void**)&wol, g_wol);

    cudaFuncSetAttribute(gemm_qkv_kernel, cudaFuncAttributeMaxDynamicSharedMemorySize, GEMM_SMEM);
    cudaFuncSetAttribute(gemm_out_kernel, cudaFuncAttributeMaxDynamicSharedMemorySize, GEMM_SMEM);
    cudaFuncSetAttribute(attn_mma_kernel, cudaFuncAttributeMaxDynamicSharedMemorySize, FA_SMEM);

    const int n4x = NELEM / 4;
    const int n4w = (DM * DM) / 4;
    split_kernel<<<n4x / 256, 256>>>(x, xh, xl, n4x, 1.0f);
    split_kernel<<<n4w / 256, 256>>>(Wq, wqh, wql, n4w, 1.0f);
    split_kernel<<<n4w / 256, 256>>>(Wk, wkh, wkl, n4w, 1.0f);
    split_kernel<<<n4w / 256, 256>>>(Wv, wvh, wvl, n4w, 1.0f);
    split_kernel<<<n4w / 256, 256>>>(Wo, woh, wol, n4w, 1.0f);

    // fused Q/K/V projections (Q pre-scaled into log2-softmax domain)
    const float qscale = 0.125f * 1.44269504088896341f;
    dim3 ggrid(DM / GBN, MROWS / GBM, 3);   // (8, 64, 3)
    gemm_qkv_kernel<<<ggrid, 256, GEMM_SMEM>>>(xh, xl, qscale);

    dim3 agrid(T_SZ / 128, NH, B_SZ);       // (16, 16, 4)
    attn_mma_kernel<<<agrid, 256, FA_SMEM>>>(qh, ql, kh, kl, vh, vl, oh, ol);

    dim3 ogrid(DM / GBN, MROWS / GBM);
    gemm_out_kernel<<<ogrid, 256, GEMM_SMEM>>>(oh, ol, out, bo);
}

// round 15
// speedup vs baseline: 10.7665x; 2.7457x over previous
#include <cuda_runtime.h>
#include <cuda_fp16.h>
#include <cstdint>
#include <math.h>

// Problem constants
#define B_SZ 4
#define T_SZ 2048
#define DM   1024
#define NH   16
#define HD   64
#define MROWS (B_SZ * T_SZ)   // 8192
#define NELEM (MROWS * DM)

// ---------------- scratch (allocation-free) ----------------
__device__ __half g_xh[NELEM];
__device__ __half g_oh[NELEM];
__device__ __half g_qh[NELEM];
__device__ __half g_kh[NELEM];
__device__ __half g_vh[NELEM];
__device__ __half g_wq[DM * DM];
__device__ __half g_wk[DM * DM];
__device__ __half g_wv[DM * DM];
__device__ __half g_wo[DM * DM];

// ---------------- helpers ----------------
__device__ __forceinline__ uint32_t smem_u32(const void* p) {
    uint32_t a;
    asm("{ .reg .u64 t; cvta.to.shared.u64 t, %1; cvt.u32.u64 %0, t; }" : "=r"(a) : "l"(p));
    return a;
}

#define LDSM_X4(r, addr) \
    asm volatile("ldmatrix.sync.aligned.m8n8.x4.shared.b16 {%0,%1,%2,%3}, [%4];" \
        : "=r"((r)[0]), "=r"((r)[1]), "=r"((r)[2]), "=r"((r)[3]) : "r"(addr))

#define LDSM_X4_T(r, addr) \
    asm volatile("ldmatrix.sync.aligned.m8n8.x4.trans.shared.b16 {%0,%1,%2,%3}, [%4];" \
        : "=r"((r)[0]), "=r"((r)[1]), "=r"((r)[2]), "=r"((r)[3]) : "r"(addr))

// D += A*B  (m16n8k16, fp16 in, fp32 accum)
#define MMA_F16(d, a, b0, b1) \
    asm volatile("mma.sync.aligned.m16n8k16.row.col.f32.f16.f16.f32 " \
        "{%0,%1,%2,%3}, {%4,%5,%6,%7}, {%8,%9}, {%0,%1,%2,%3};" \
        : "+f"((d)[0]), "+f"((d)[1]), "+f"((d)[2]), "+f"((d)[3]) \
        : "r"((a)[0]), "r"((a)[1]), "r"((a)[2]), "r"((a)[3]), "r"(b0), "r"(b1))

#define CP_ASYNC16(saddr, gptr) \
    asm volatile("cp.async.cg.shared.global [%0], [%1], 16;" :: "r"(saddr), "l"(gptr))
#define CP_COMMIT() asm volatile("cp.async.commit_group;" ::: "memory")
#define CP_WAIT0()  asm volatile("cp.async.wait_group 0;" ::: "memory")
#define CP_WAIT1()  asm volatile("cp.async.wait_group 1;" ::: "memory")

__device__ __forceinline__ uint32_t pack_h2(float a, float b) {
    __half2 h = __floats2half2_rn(a, b);   // low = a, high = b
    return *(uint32_t*)&h;
}

// ---------------- fp32 -> fp16 convert kernels ----------------
__global__ __launch_bounds__(256)
void cvt_kernel(const float* __restrict__ src, __half* __restrict__ dst, int n4)
{
    int i = blockIdx.x * blockDim.x + threadIdx.x;
    if (i >= n4) return;
    float4 v = ((const float4*)src)[i];
    ((uint32_t*)dst)[2*i]   = pack_h2(v.x, v.y);
    ((uint32_t*)dst)[2*i+1] = pack_h2(v.z, v.w);
}

// all 4 weights in one launch (grid.z selects)
__global__ __launch_bounds__(256)
void cvtw_kernel(const float* __restrict__ W0, const float* __restrict__ W1,
                 const float* __restrict__ W2, const float* __restrict__ W3, int n4)
{
    int i = blockIdx.x * blockDim.x + threadIdx.x;
    if (i >= n4) return;
    const int z = blockIdx.z;
    const float* src = (z == 0) ? W0 : (z == 1) ? W1 : (z == 2) ? W2 : W3;
    __half* dst = (z == 0) ? g_wq : (z == 1) ? g_wk : (z == 2) ? g_wv : g_wo;
    float4 v = ((const float4*)src)[i];
    ((uint32_t*)dst)[2*i]   = pack_h2(v.x, v.y);
    ((uint32_t*)dst)[2*i+1] = pack_h2(v.z, v.w);
}

// ---------------- cp.async double-buffered fp16 NT GEMM ----------------
// C[M,ldc] 128x128 tile = A * B^T, K-major. 128B smem rows, XOR-8 swizzle.
#define GBM 128
#define GBN 128
#define GBK 64
#define OPB (GBM * GBK * 2)       // 16384
#define OFF_A 0
#define OFF_B OPB
#define G_STAGE (2 * OPB)         // 32768
#define GEMM_SMEM (2 * G_STAGE)   // 65536

__device__ __forceinline__ uint32_t fsw(int r, int c) {   // 128B-row swizzle
    return (uint32_t)(r * 128 + ((c ^ (r & 7)) << 4));
}

__device__ __forceinline__ void gemm_prefetch(
    uint32_t stage_base, const __half* A, const __half* B,
    int row0, int col0, int Kdim, int koff, int tid)
{
    const int cc = tid & 7;
    const int rr0 = tid >> 3;   // 0..31
    #pragma unroll
    for (int i = 0; i < 4; ++i) {
        const int rr = rr0 + i * 32;
        const uint32_t so = fsw(rr, cc);
        CP_ASYNC16(stage_base + OFF_A + so, A + (size_t)(row0 + rr) * Kdim + koff + cc * 8);
        CP_ASYNC16(stage_base + OFF_B + so, B + (size_t)(col0 + rr) * Kdim + koff + cc * 8);
    }
}

// Shared body. If Ch != nullptr: write fp16 of cscale*acc; else fp32 C (+bias).
__device__ __forceinline__ void gemm_body(
    const __half* __restrict__ A, const __half* __restrict__ B,
    float* __restrict__ C, const float* __restrict__ bias,
    __half* __restrict__ Ch, float cscale, int Kdim, int ldc, char* smem)
{
    const uint32_t sb = smem_u32(smem);
    const int tid  = threadIdx.x;
    const int warp = tid >> 5;
    const int lane = tid & 31;
    const int wm = warp & 1;
    const int wn = warp >> 1;
    const int row0 = blockIdx.y * GBM;
    const int col0 = blockIdx.x * GBN;

    float acc[4][4][4];
    #pragma unroll
    for (int a = 0; a < 4; ++a)
        #pragma unroll
        for (int b = 0; b < 4; ++b)
            #pragma unroll
            for (int c = 0; c < 4; ++c) acc[a][b][c] = 0.f;

    const int sub = lane >> 3;
    const int l7  = lane & 7;
    const int nchunk = Kdim / GBK;   // 16

    gemm_prefetch(sb, A, B, row0, col0, Kdim, 0, tid);
    CP_COMMIT();

    for (int kc = 0; kc < nchunk; ++kc) {
        const int s = kc & 1;
        if (kc + 1 < nchunk) {
            gemm_prefetch(sb + (1 - s) * G_STAGE, A, B, row0, col0, Kdim, (kc + 1) * GBK, tid);
            CP_COMMIT();
            CP_WAIT1();
        } else {
            CP_WAIT0();
        }
        __syncthreads();

        const uint32_t ss = sb + s * G_STAGE;
        #pragma unroll
        for (int ks = 0; ks < 4; ++ks) {
            uint32_t af[4][4], bf[4][2];
            #pragma unroll
            for (int mt = 0; mt < 4; ++mt) {
                const int r  = wm * 64 + mt * 16 + ((sub & 1) << 3) + l7;
                const int ch = ks * 2 + (sub >> 1);
                LDSM_X4(af[mt], ss + OFF_A + fsw(r, ch));
            }
            #pragma unroll
            for (int np = 0; np < 2; ++np) {
                const int r  = wn * 32 + np * 16 + ((sub >> 1) << 3) + l7;
                const int ch = ks * 2 + (sub & 1);
                uint32_t t[4];
                LDSM_X4(t, ss + OFF_B + fsw(r, ch));
                bf[np*2][0]   = t[0]; bf[np*2][1]   = t[1];
                bf[np*2+1][0] = t[2]; bf[np*2+1][1] = t[3];
            }
            #pragma unroll
            for (int mt = 0; mt < 4; ++mt)
                #pragma unroll
                for (int nt = 0; nt < 4; ++nt)
                    MMA_F16(acc[mt][nt], af[mt], bf[nt][0], bf[nt][1]);
        }
        __syncthreads();
    }

    const int er = lane >> 2;
    const int ec = (lane & 3) * 2;
    if (Ch) {
        #pragma unroll
        for (int mt = 0; mt < 4; ++mt) {
            const int grow = row0 + wm * 64 + mt * 16 + er;
            #pragma unroll
            for (int nt = 0; nt < 4; ++nt) {
                const int gcol = col0 + wn * 32 + nt * 8 + ec;
                *(uint32_t*)&Ch[(size_t)grow * ldc + gcol] =
                    pack_h2(acc[mt][nt][0] * cscale, acc[mt][nt][1] * cscale);
                *(uint32_t*)&Ch[(size_t)(grow + 8) * ldc + gcol] =
                    pack_h2(acc[mt][nt][2] * cscale, acc[mt][nt][3] * cscale);
            }
        }
    } else {
        #pragma unroll
        for (int mt = 0; mt < 4; ++mt) {
            const int grow = row0 + wm * 64 + mt * 16 + er;
            #pragma unroll
            for (int nt = 0; nt < 4; ++nt) {
                const int gcol = col0 + wn * 32 + nt * 8 + ec;
                float bx = 0.f, by = 0.f;
                if (bias) { bx = bias[gcol]; by = bias[gcol + 1]; }
                *(float2*)&C[(size_t)grow * ldc + gcol] =
                    make_float2(acc[mt][nt][0] + bx, acc[mt][nt][1] + by);
                *(float2*)&C[(size_t)(grow + 8) * ldc + gcol] =
                    make_float2(acc[mt][nt][2] + bx, acc[mt][nt][3] + by);
            }
        }
    }
}

// Fused Q/K/V projection: grid.z = 0/1/2.
__global__ __launch_bounds__(256, 2)
void gemm_qkv_kernel(const __half* __restrict__ xh, float qscale)
{
    extern __shared__ __align__(128) char smem[];
    const int z = blockIdx.z;
    const __half* B = (z == 0) ? g_wq : (z == 1) ? g_wk : g_wv;
    __half* Ch = (z == 0) ? g_qh : (z == 1) ? g_kh : g_vh;
    const float cs = (z == 0) ? qscale : 1.0f;
    gemm_body(xh, B, nullptr, nullptr, Ch, cs, DM, DM, smem);
}

__global__ __launch_bounds__(256, 2)
void gemm_out_kernel(const __half* __restrict__ Ah, float* __restrict__ C,
                     const float* __restrict__ bias)
{
    extern __shared__ __align__(128) char smem[];
    gemm_body(Ah, g_wo, C, bias, nullptr, 1.0f, DM, DM, smem);
}

// ---------------- cp.async double-buffered fp16 flash attention ----------------
#define FA_BN 64
#define FA_TILEB (FA_BN * 128)        // 8192 (128B rows)
#define FA_STAGE (2 * FA_TILEB)       // 16384: K | V
#define FA_SMEM (2 * FA_STAGE)        // 32768

__device__ __forceinline__ void attn_prefetch(
    uint32_t stage_base, const __half* K, const __half* V,
    size_t rowbase, int colbase, int key0, int tid)
{
    #pragma unroll
    for (int i = 0; i < 2; ++i) {
        int u = tid + i * 256;
        int r = u >> 3, c = u & 7;
        const size_t g = (rowbase + key0 + r) * DM + colbase + c * 8;
        const uint32_t so = fsw(r, c);
        CP_ASYNC16(stage_base + so,            K + g);
        CP_ASYNC16(stage_base + FA_TILEB + so, V + g);
    }
}

__global__ __launch_bounds__(256, 2)
void attn_mma_kernel(const __half* __restrict__ Q, const __half* __restrict__ K,
                     const __half* __restrict__ V, __half* __restrict__ O)
{
    extern __shared__ __align__(128) char sm[];
    const uint32_t sb = smem_u32(sm);

    const int tid  = threadIdx.x;
    const int warp = tid >> 5;
    const int lane = tid & 31;
    const int sub  = lane >> 3;
    const int l7   = lane & 7;
    const int h = blockIdx.y;
    const int b = blockIdx.z;
    const int q0 = blockIdx.x * 128;

    const size_t rowbase = (size_t)b * T_SZ;
    const int    colbase = h * HD;

    // stage Q tile (128 x 64 fp16) through buffer 0, keep A fragments
    uint32_t qf[4][4];
    {
        #pragma unroll
        for (int i = 0; i < 4; ++i) {
            int u = tid + i * 256;
            int r = u >> 3, c = u & 7;
            const uint4 v = *(const uint4*)(Q + (rowbase + q0 + r) * DM + colbase + c * 8);
            *(uint4*)(sm + fsw(r, c)) = v;
        }
        __syncthreads();
        #pragma unroll
        for (int t = 0; t < 4; ++t) {
            const int r  = warp * 16 + ((sub & 1) << 3) + l7;
            const int ch = t * 2 + (sub >> 1);
            LDSM_X4(qf[t], sb + fsw(r, ch));
        }
        __syncthreads();
    }

    float acc[8][4];
    #pragma unroll
    for (int j = 0; j < 8; ++j)
        #pragma unroll
        for (int c = 0; c < 4; ++c) acc[j][c] = 0.f;
    float m0 = -1e30f, m1 = -1e30f, l0 = 0.f, l1 = 0.f;

    attn_prefetch(sb, K, V, rowbase, colbase, 0, tid);
    CP_COMMIT();

    const int ntiles = T_SZ / FA_BN;   // 32
    for (int kt = 0; kt < ntiles; ++kt) {
        const int s = kt & 1;
        if (kt + 1 < ntiles) {
            attn_prefetch(sb + (1 - s) * FA_STAGE, K, V, rowbase, colbase, (kt + 1) * FA_BN, tid);
            CP_COMMIT();
            CP_WAIT1();
        } else {
            CP_WAIT0();
        }
        __syncthreads();
        const uint32_t ss = sb + s * FA_STAGE;

        // S = Q K^T
        float st[8][4];
        #pragma unroll
        for (int j = 0; j < 8; ++j)
            #pragma unroll
            for (int c = 0; c < 4; ++c) st[j][c] = 0.f;

        #pragma unroll
        for (int np = 0; np < 4; ++np) {
            #pragma unroll
            for (int t = 0; t < 4; ++t) {
                const int r  = np * 16 + ((sub >> 1) << 3) + l7;
                const int ch = t * 2 + (sub & 1);
                uint32_t e[4];
                LDSM_X4(e, ss + fsw(r, ch));
                MMA_F16(st[np*2],   qf[t], e[0], e[1]);
                MMA_F16(st[np*2+1], qf[t], e[2], e[3]);
            }
        }

        // online softmax (log2 domain; Q pre-scaled by 0.125*log2e)
        float tm0 = st[0][0], tm1 = st[0][2];
        #pragma unroll
        for (int j = 0; j < 8; ++j) {
            tm0 = fmaxf(tm0, fmaxf(st[j][0], st[j][1]));
            tm1 = fmaxf(tm1, fmaxf(st[j][2], st[j][3]));
        }
        tm0 = fmaxf(tm0, __shfl_xor_sync(0xffffffffu, tm0, 1));
        tm0 = fmaxf(tm0, __shfl_xor_sync(0xffffffffu, tm0, 2));
        tm1 = fmaxf(tm1, __shfl_xor_sync(0xffffffffu, tm1, 1));
        tm1 = fmaxf(tm1, __shfl_xor_sync(0xffffffffu, tm1, 2));
        const float nm0 = fmaxf(m0, tm0), nm1 = fmaxf(m1, tm1);
        const float c0 = exp2f(m0 - nm0), c1 = exp2f(m1 - nm1);
        m0 = nm0; m1 = nm1;
        if (__any_sync(0xffffffffu, (c0 != 1.f) | (c1 != 1.f))) {
            l0 *= c0; l1 *= c1;
            #pragma unroll
            for (int j = 0; j < 8; ++j) {
                acc[j][0] *= c0; acc[j][1] *= c0;
                acc[j][2] *= c1; acc[j][3] *= c1;
            }
        }
        #pragma unroll
        for (int j = 0; j < 8; ++j) {
            st[j][0] = exp2f(st[j][0] - m0);
            st[j][1] = exp2f(st[j][1] - m0);
            st[j][2] = exp2f(st[j][2] - m1);
            st[j][3] = exp2f(st[j][3] - m1);
            l0 += st[j][0] + st[j][1];
            l1 += st[j][2] + st[j][3];
        }

        // pack P into fp16 A fragments
        uint32_t pf[4][4];
        #pragma unroll
        for (int t = 0; t < 4; ++t) {
            pf[t][0] = pack_h2(st[2*t][0],   st[2*t][1]);
            pf[t][1] = pack_h2(st[2*t][2],   st[2*t][3]);
            pf[t][2] = pack_h2(st[2*t+1][0], st[2*t+1][1]);
            pf[t][3] = pack_h2(st[2*t+1][2], st[2*t+1][3]);
        }

        // acc += P V
        #pragma unroll
        for (int t = 0; t < 4; ++t) {
            #pragma unroll
            for (int dp = 0; dp < 4; ++dp) {
                const int r  = t * 16 + ((sub & 1) << 3) + l7;
                const int ch = dp * 2 + (sub >> 1);
                uint32_t v[4];
                LDSM_X4_T(v, ss + FA_TILEB + fsw(r, ch));
                MMA_F16(acc[dp*2],   pf[t], v[0], v[1]);
                MMA_F16(acc[dp*2+1], pf[t], v[2], v[3]);
            }
        }
        __syncthreads();
    }

    // finalize, write fp16 O
    l0 += __shfl_xor_sync(0xffffffffu, l0, 1);
    l0 += __shfl_xor_sync(0xffffffffu, l0, 2);
    l1 += __shfl_xor_sync(0xffffffffu, l1, 1);
    l1 += __shfl_xor_sync(0xffffffffu, l1, 2);
    const float inv0 = 1.f / (l0 + 1e-8f);
    const float inv1 = 1.f / (l1 + 1e-8f);

    const int r0 = q0 + warp * 16 + (lane >> 2);
    const int ec = (lane & 3) * 2;
    #pragma unroll
    for (int j = 0; j < 8; ++j) {
        const int gcol = colbase + j * 8 + ec;
        *(uint32_t*)&O[(rowbase + r0) * DM + gcol] =
            pack_h2(acc[j][0] * inv0, acc[j][1] * inv0);
        *(uint32_t*)&O[(rowbase + r0 + 8) * DM + gcol] =
            pack_h2(acc[j][2] * inv1, acc[j][3] * inv1);
    }
}

// ---------------- launch ----------------
extern "C" void kernel_launch(void* const* d_in, const int* in_sizes, int n_in,
                              void* d_out, int out_size)
{
    const float* x  = (const float*)d_in[0];
    const float* Wq = (const float*)d_in[1];
    const float* Wk = (const float*)d_in[2];
    const float* Wv = (const float*)d_in[3];
    const float* Wo = (const float*)d_in[4];
    const float* bo = (const float*)d_in[5];
    float* out = (float*)d_out;

    __half *xh, *oh, *qh, *kh, *vh;
    cudaGetSymbolAddress((void**)&xh, g_xh);
    cudaGetSymbolAddress((void**)&oh, g_oh);
    cudaGetSymbolAddress((void**)&qh, g_qh);
    cudaGetSymbolAddress((void**)&kh, g_kh);
    cudaGetSymbolAddress((void**)&vh, g_vh);

    cudaFuncSetAttribute(gemm_qkv_kernel, cudaFuncAttributeMaxDynamicSharedMemorySize, GEMM_SMEM);
    cudaFuncSetAttribute(gemm_out_kernel, cudaFuncAttributeMaxDynamicSharedMemorySize, GEMM_SMEM);
    cudaFuncSetAttribute(attn_mma_kernel, cudaFuncAttributeMaxDynamicSharedMemorySize, FA_SMEM);

    const int n4x = NELEM / 4;
    const int n4w = (DM * DM) / 4;
    cvt_kernel<<<n4x / 256, 256>>>(x, xh, n4x);
    dim3 wgrid(n4w / 256, 1, 4);
    cvtw_kernel<<<wgrid, 256>>>(Wq, Wk, Wv, Wo, n4w);

    // fused Q/K/V projections (Q pre-scaled into log2-softmax domain)
    const float qscale = 0.125f * 1.44269504088896341f;
    dim3 ggrid(DM / GBN, MROWS / GBM, 3);   // (8, 64, 3)
    gemm_qkv_kernel<<<ggrid, 256, GEMM_SMEM>>>(xh, qscale);

    dim3 agrid(T_SZ / 128, NH, B_SZ);       // (16, 16, 4)
    attn_mma_kernel<<<agrid, 256, FA_SMEM>>>(qh, kh, vh, oh);

    dim3 ogrid(DM / GBN, MROWS / GBM);
    gemm_out_kernel<<<ogrid, 256, GEMM_SMEM>>>(oh, out, bo);
}